// round 1
// baseline (speedup 1.0000x reference)
#include <cuda_runtime.h>
#include <cstdint>
#include <math.h>

// Problem constants
#define Bp   4096
#define Dd   19
#define Ff   64
#define NCc  256
#define HIDh 32
#define SQq  16
#define Nn   (Bp + NCc)

// K3 tiling
#define JT   128            // j per tile
#define NJT  (Nn / JT)      // 34
#define IT   16             // centers per block
#define NIT  (NCc / IT)     // 16

// Output offsets (floats)
#define OUT_GS  0
#define OUT_GE  (Bp * Dd)
#define OUT_GPE ((Bp + NCc) * Dd)
#define OUT_GL  (((2 * Bp) + NCc) * Dd)

// -------- device scratch (no allocations allowed) --------
__device__ float g_x_all[Nn * Dd];
__device__ float g_e[Nn * Dd];
__device__ float g_sq[Nn];
__device__ float g_g[Nn * HIDh];
__device__ float g_partial[NJT * NCc * HIDh];
__device__ float g_ge[NCc * Dd];
__device__ float g_sc[NCc * Dd];

// ============================================================
// K1: per patient: x_avg (mean over F), e = exp(1-dc), sq, g = x_avg @ gcn_w
// grid = Bp, block = 128
// ============================================================
__global__ void k1_patients(const float* __restrict__ x,
                            const float* __restrict__ dc,
                            const float* __restrict__ gcn_w) {
    __shared__ float sxa[Dd];
    __shared__ float sw[Dd * HIDh];
    int b = blockIdx.x;
    int tid = threadIdx.x;

    for (int i = tid; i < Dd * HIDh; i += 128) sw[i] = gcn_w[i];

    int w = tid >> 5, lane = tid & 31;
    const float* xb = x + (size_t)b * (Dd * Ff);
    for (int d = w; d < Dd; d += 4) {
        float v = xb[d * Ff + lane] + xb[d * Ff + lane + 32];
        v += __shfl_down_sync(0xffffffffu, v, 16);
        v += __shfl_down_sync(0xffffffffu, v, 8);
        v += __shfl_down_sync(0xffffffffu, v, 4);
        v += __shfl_down_sync(0xffffffffu, v, 2);
        v += __shfl_down_sync(0xffffffffu, v, 1);
        if (lane == 0) sxa[d] = v * (1.0f / 64.0f);
    }
    __syncthreads();

    if (tid < Dd) {
        float xa = sxa[tid];
        g_x_all[b * Dd + tid] = xa;
        g_e[b * Dd + tid] = expf(1.0f - dc[b * Dd + tid]);
    }
    if (tid == 32) {
        float s = 0.0f;
        #pragma unroll
        for (int k = 0; k < Dd; k++) s += sxa[k] * sxa[k];
        g_sq[b] = s;
    }
    if (tid >= 64 && tid < 64 + HIDh) {
        int h = tid - 64;
        float acc = 0.0f;
        #pragma unroll
        for (int k = 0; k < Dd; k++) acc += sxa[k] * sw[k * HIDh + h];
        g_g[b * HIDh + h] = acc;
    }
}

// ============================================================
// K2: centers_p = centers @ proj_w + proj_b; e, sq, g for center rows
// grid = 1, block = 256 (thread c = one center)
// ============================================================
__global__ void k2_centers(const float* __restrict__ centers,
                           const float* __restrict__ proj_w,
                           const float* __restrict__ proj_b,
                           const float* __restrict__ cc,
                           const float* __restrict__ gcn_w) {
    __shared__ float spw[61 * Dd];
    __shared__ float spb[Dd];
    __shared__ float sgw[Dd * HIDh];
    int tid = threadIdx.x;
    for (int i = tid; i < 61 * Dd; i += 256) spw[i] = proj_w[i];
    if (tid < Dd) spb[tid] = proj_b[tid];
    for (int i = tid; i < Dd * HIDh; i += 256) sgw[i] = gcn_w[i];
    __syncthreads();

    int c = tid;
    float cp[Dd];
    #pragma unroll
    for (int k = 0; k < Dd; k++) cp[k] = spb[k];
    for (int m = 0; m < 61; m++) {
        float cm = centers[c * 61 + m];
        #pragma unroll
        for (int k = 0; k < Dd; k++) cp[k] += cm * spw[m * Dd + k];
    }
    int row = Bp + c;
    float s = 0.0f;
    #pragma unroll
    for (int k = 0; k < Dd; k++) {
        g_x_all[row * Dd + k] = cp[k];
        s += cp[k] * cp[k];
        g_e[row * Dd + k] = expf(1.0f - cc[c * Dd + k]);
    }
    g_sq[row] = s;
    #pragma unroll
    for (int h = 0; h < HIDh; h++) {
        float acc = 0.0f;
        #pragma unroll
        for (int k = 0; k < Dd; k++) acc += cp[k] * sgw[k * HIDh + h];
        g_g[row * HIDh + h] = acc;
    }
}

// ============================================================
// K3: fused adjacency generation + adj@g accumulation for center rows.
// grid = (NJT, NIT), block = 256. Thread (ci, s): ci = tid>>4 center-in-tile,
// s = tid&15 j-slot. Deterministic partial sums per (jt, center, h).
// ============================================================
__global__ void k3_main(const float* __restrict__ p_ptr) {
    __shared__ float sx[JT * Dd];
    __shared__ float se[JT * Dd];
    __shared__ float sg[JT * 33];   // padded: stride 33 avoids 16-way conflicts
    __shared__ float ssq[JT];

    int tid = threadIdx.x;
    int jt = blockIdx.x, it = blockIdx.y;
    int j0 = jt * JT;

    for (int i = tid; i < JT * Dd; i += 256) {
        sx[i] = g_x_all[j0 * Dd + i];
        se[i] = g_e[j0 * Dd + i];
    }
    for (int i = tid; i < JT * HIDh; i += 256) {
        int j = i >> 5, h = i & 31;
        sg[j * 33 + h] = g_g[j0 * HIDh + i];
    }
    if (tid < JT) ssq[tid] = g_sq[j0 + tid];

    int ci = tid >> 4, s = tid & 15;
    int cg = Bp + it * IT + ci;
    float xc[Dd], ec[Dd];
    #pragma unroll
    for (int k = 0; k < Dd; k++) {
        xc[k] = g_x_all[cg * Dd + k];
        ec[k] = g_e[cg * Dd + k];
    }
    float sqc = g_sq[cg];
    float p = *p_ptr;
    float c1 = 1.0f - p;
    __syncthreads();

    float acc[HIDh];
    #pragma unroll
    for (int h = 0; h < HIDh; h++) acc[h] = 0.0f;

    #pragma unroll 2
    for (int t = 0; t < JT / 16; t++) {
        int j = s + 16 * t;
        float dx = 0.0f, de = 0.0f;
        #pragma unroll
        for (int k = 0; k < Dd; k++) {
            dx += xc[k] * sx[j * Dd + k];
            de += ec[k] * se[j * Dd + k];
        }
        int jg = j0 + j;
        float a;
        if (jg == cg) {
            a = 1.0f;
        } else {
            float denom = c1 * (sqc + ssq[j] - 2.0f * dx) + p * de;
            a = (float)Dd / denom;
        }
        #pragma unroll
        for (int h = 0; h < HIDh; h++) acc[h] += a * sg[j * 33 + h];
    }

    // reduce over the 16 j-slots (lanes 0-15 / 16-31 of each warp)
    #pragma unroll
    for (int h = 0; h < HIDh; h++) {
        acc[h] += __shfl_down_sync(0xffffffffu, acc[h], 8);
        acc[h] += __shfl_down_sync(0xffffffffu, acc[h], 4);
        acc[h] += __shfl_down_sync(0xffffffffu, acc[h], 2);
        acc[h] += __shfl_down_sync(0xffffffffu, acc[h], 1);
    }
    if (s == 0) {
        int c = it * IT + ci;
        #pragma unroll
        for (int h = 0; h < HIDh; h++)
            g_partial[(jt * NCc + c) * HIDh + h] = acc[h];
    }
}

// ============================================================
// K4: reduce partials -> emb (sigmoid(out MLP)) -> group_embedding (output)
//     -> gelu/imp chain -> scores. grid = 8, block = 32 (thread = center)
// ============================================================
__global__ void k4_emb(const float* __restrict__ gcn_b,
                       const float* __restrict__ out_w,
                       const float* __restrict__ out_b,
                       const float* __restrict__ w1,
                       const float* __restrict__ b1,
                       const float* __restrict__ w2,
                       const float* __restrict__ b2,
                       float* __restrict__ out) {
    int c = blockIdx.x * 32 + threadIdx.x;

    float eh[HIDh];
    #pragma unroll
    for (int h = 0; h < HIDh; h++) eh[h] = gcn_b[h];
    for (int jt = 0; jt < NJT; jt++) {
        const float* pp = &g_partial[(jt * NCc + c) * HIDh];
        #pragma unroll
        for (int h = 0; h < HIDh; h++) eh[h] += pp[h];
    }

    float emb[Dd];
    #pragma unroll
    for (int k = 0; k < Dd; k++) {
        float v = out_b[k];
        #pragma unroll
        for (int h = 0; h < HIDh; h++) v += eh[h] * out_w[h * Dd + k];
        v = 1.0f / (1.0f + expf(-v));
        emb[k] = v;
        g_ge[c * Dd + k] = v;
        out[OUT_GE + c * Dd + k] = v;
    }

    float hq[SQq];
    #pragma unroll
    for (int q = 0; q < SQq; q++) {
        float v = b1[q];
        #pragma unroll
        for (int k = 0; k < Dd; k++) v += emb[k] * w1[k * SQq + q];
        hq[q] = 0.5f * v * (1.0f + erff(v * 0.70710678118654752f));  // exact gelu
    }
    #pragma unroll
    for (int k = 0; k < Dd; k++) {
        float v = b2[k];
        #pragma unroll
        for (int q = 0; q < SQq; q++) v += hq[q] * w2[q * Dd + k];
        g_sc[c * Dd + k] = 1.0f / (1.0f + expf(-v));
    }
}

// ============================================================
// K5: per-patient argmin of denom over 256 centers (== argmax of sim, with
// first-index tie-break via packed key) + gather of outputs.
// grid = Bp/32, block = 256 (8 lanes per patient)
// ============================================================
__global__ void k5_gather(const float* __restrict__ p_ptr,
                          float* __restrict__ out) {
    __shared__ float scx[NCc * Dd];
    __shared__ float sce[NCc * Dd];
    __shared__ float scsq[NCc];
    int tid = threadIdx.x;
    for (int i = tid; i < NCc * Dd; i += 256) {
        scx[i] = g_x_all[Bp * Dd + i];
        sce[i] = g_e[Bp * Dd + i];
    }
    if (tid < NCc) scsq[tid] = g_sq[Bp + tid];
    float p = *p_ptr;
    float c1 = 1.0f - p;
    __syncthreads();

    int pl = tid >> 3, l8 = tid & 7;
    int jp = blockIdx.x * 32 + pl;

    float xp[Dd], ep[Dd];
    #pragma unroll
    for (int k = 0; k < Dd; k++) {
        xp[k] = g_x_all[jp * Dd + k];
        ep[k] = g_e[jp * Dd + k];
    }
    float sqp = g_sq[jp];

    unsigned long long best = 0xFFFFFFFFFFFFFFFFull;
    for (int c = l8; c < NCc; c += 8) {
        float dx = 0.0f, de = 0.0f;
        #pragma unroll
        for (int k = 0; k < Dd; k++) {
            dx += xp[k] * scx[c * Dd + k];
            de += ep[k] * sce[c * Dd + k];
        }
        float denom = c1 * (sqp + scsq[c] - 2.0f * dx) + p * de;
        unsigned long long key =
            (((unsigned long long)__float_as_uint(denom)) << 32) | (unsigned)c;
        if (key < best) best = key;
    }
    unsigned long long o;
    o = __shfl_xor_sync(0xffffffffu, best, 1); if (o < best) best = o;
    o = __shfl_xor_sync(0xffffffffu, best, 2); if (o < best) best = o;
    o = __shfl_xor_sync(0xffffffffu, best, 4); if (o < best) best = o;

    int label = (int)(unsigned)(best & 0xFFFFFFFFull);
    for (int k = l8; k < Dd; k += 8) {
        out[OUT_GS + jp * Dd + k] = g_sc[label * Dd + k];
        out[OUT_GPE + jp * Dd + k] = g_ge[label * Dd + k];
    }
    if (l8 == 0) out[OUT_GL + jp] = (float)label;
}

// ============================================================
extern "C" void kernel_launch(void* const* d_in, const int* in_sizes, int n_in,
                              void* d_out, int out_size) {
    const float* x        = (const float*)d_in[0];
    const float* dc       = (const float*)d_in[1];
    const float* centers  = (const float*)d_in[2];
    const float* proj_w   = (const float*)d_in[3];
    const float* proj_b   = (const float*)d_in[4];
    const float* dc_param = (const float*)d_in[5];
    const float* cc       = (const float*)d_in[6];
    const float* gcn_w    = (const float*)d_in[7];
    const float* gcn_b    = (const float*)d_in[8];
    const float* out_w    = (const float*)d_in[9];
    const float* out_b    = (const float*)d_in[10];
    const float* w1       = (const float*)d_in[11];
    const float* b1       = (const float*)d_in[12];
    const float* w2       = (const float*)d_in[13];
    const float* b2       = (const float*)d_in[14];
    float* out = (float*)d_out;

    k1_patients<<<Bp, 128>>>(x, dc, gcn_w);
    k2_centers<<<1, 256>>>(centers, proj_w, proj_b, cc, gcn_w);
    k3_main<<<dim3(NJT, NIT), 256>>>(dc_param);
    k4_emb<<<8, 32>>>(gcn_b, out_w, out_b, w1, b1, w2, b2, out);
    k5_gather<<<Bp / 32, 256>>>(dc_param, out);
}

// round 2
// speedup vs baseline: 1.6658x; 1.6658x over previous
#include <cuda_runtime.h>
#include <cstdint>
#include <math.h>

// Problem constants
#define Bp   4096
#define Dd   19
#define Ff   64
#define NCc  256
#define HIDh 32
#define SQq  16
#define Nn   (Bp + NCc)

// K3 tiling
#define JT   128            // j per tile
#define NJT  (Nn / JT)      // 34
#define IT   16             // centers per block
#define NIT  (NCc / IT)     // 16

// Output offsets (floats)
#define OUT_GS  0
#define OUT_GE  (Bp * Dd)
#define OUT_GPE ((Bp + NCc) * Dd)
#define OUT_GL  (((2 * Bp) + NCc) * Dd)

// -------- device scratch (no allocations allowed) --------
__device__ float g_x_all[Nn * Dd];
__device__ float g_e[Nn * Dd];
__device__ float g_sq[Nn];
__device__ float g_g[Nn * HIDh];
__device__ float g_partial[NJT * NCc * HIDh];
__device__ float g_ge[NCc * Dd];
__device__ float g_sc[NCc * Dd];

// ============================================================
// K1: per patient: x_avg (mean over F), e = exp(1-dc), sq, g = x_avg @ gcn_w
// grid = Bp, block = 128
// ============================================================
__global__ void k1_patients(const float* __restrict__ x,
                            const float* __restrict__ dc,
                            const float* __restrict__ gcn_w) {
    __shared__ float sxa[Dd];
    __shared__ float sw[Dd * HIDh];
    int b = blockIdx.x;
    int tid = threadIdx.x;

    for (int i = tid; i < Dd * HIDh; i += 128) sw[i] = gcn_w[i];

    int w = tid >> 5, lane = tid & 31;
    const float* xb = x + (size_t)b * (Dd * Ff);
    for (int d = w; d < Dd; d += 4) {
        float v = xb[d * Ff + lane] + xb[d * Ff + lane + 32];
        v += __shfl_down_sync(0xffffffffu, v, 16);
        v += __shfl_down_sync(0xffffffffu, v, 8);
        v += __shfl_down_sync(0xffffffffu, v, 4);
        v += __shfl_down_sync(0xffffffffu, v, 2);
        v += __shfl_down_sync(0xffffffffu, v, 1);
        if (lane == 0) sxa[d] = v * (1.0f / 64.0f);
    }
    __syncthreads();

    if (tid < Dd) {
        float xa = sxa[tid];
        g_x_all[b * Dd + tid] = xa;
        g_e[b * Dd + tid] = expf(1.0f - dc[b * Dd + tid]);
    }
    if (tid == 32) {
        float s = 0.0f;
        #pragma unroll
        for (int k = 0; k < Dd; k++) s += sxa[k] * sxa[k];
        g_sq[b] = s;
    }
    if (tid >= 64 && tid < 64 + HIDh) {
        int h = tid - 64;
        float acc = 0.0f;
        #pragma unroll
        for (int k = 0; k < Dd; k++) acc += sxa[k] * sw[k * HIDh + h];
        g_g[b * HIDh + h] = acc;
    }
}

// ============================================================
// K2: centers_p = centers @ proj_w + proj_b; e, sq, g for center rows
// grid = 1, block = 256 (thread c = one center)
// ============================================================
__global__ void k2_centers(const float* __restrict__ centers,
                           const float* __restrict__ proj_w,
                           const float* __restrict__ proj_b,
                           const float* __restrict__ cc,
                           const float* __restrict__ gcn_w) {
    __shared__ float spw[61 * Dd];
    __shared__ float spb[Dd];
    __shared__ float sgw[Dd * HIDh];
    int tid = threadIdx.x;
    for (int i = tid; i < 61 * Dd; i += 256) spw[i] = proj_w[i];
    if (tid < Dd) spb[tid] = proj_b[tid];
    for (int i = tid; i < Dd * HIDh; i += 256) sgw[i] = gcn_w[i];
    __syncthreads();

    int c = tid;
    float cp[Dd];
    #pragma unroll
    for (int k = 0; k < Dd; k++) cp[k] = spb[k];
    for (int m = 0; m < 61; m++) {
        float cm = centers[c * 61 + m];
        #pragma unroll
        for (int k = 0; k < Dd; k++) cp[k] += cm * spw[m * Dd + k];
    }
    int row = Bp + c;
    float s = 0.0f;
    #pragma unroll
    for (int k = 0; k < Dd; k++) {
        g_x_all[row * Dd + k] = cp[k];
        s += cp[k] * cp[k];
        g_e[row * Dd + k] = expf(1.0f - cc[c * Dd + k]);
    }
    g_sq[row] = s;
    #pragma unroll
    for (int h = 0; h < HIDh; h++) {
        float acc = 0.0f;
        #pragma unroll
        for (int k = 0; k < Dd; k++) acc += cp[k] * sgw[k * HIDh + h];
        g_g[row * HIDh + h] = acc;
    }
}

// ============================================================
// K3: fused adjacency generation + adj@g accumulation for center rows.
// grid = (NJT, NIT), block = 256. Thread (ci, s): ci = tid>>4 center-in-tile,
// s = tid&15 j-slot. Deterministic partial sums per (jt, center, h).
// ============================================================
__global__ void k3_main(const float* __restrict__ p_ptr) {
    __shared__ float sx[JT * Dd];
    __shared__ float se[JT * Dd];
    __shared__ float sg[JT * 33];   // padded: stride 33 avoids 16-way conflicts
    __shared__ float ssq[JT];

    int tid = threadIdx.x;
    int jt = blockIdx.x, it = blockIdx.y;
    int j0 = jt * JT;

    for (int i = tid; i < JT * Dd; i += 256) {
        sx[i] = g_x_all[j0 * Dd + i];
        se[i] = g_e[j0 * Dd + i];
    }
    for (int i = tid; i < JT * HIDh; i += 256) {
        int j = i >> 5, h = i & 31;
        sg[j * 33 + h] = g_g[j0 * HIDh + i];
    }
    if (tid < JT) ssq[tid] = g_sq[j0 + tid];

    int ci = tid >> 4, s = tid & 15;
    int cg = Bp + it * IT + ci;
    float xc[Dd], ec[Dd];
    #pragma unroll
    for (int k = 0; k < Dd; k++) {
        xc[k] = g_x_all[cg * Dd + k];
        ec[k] = g_e[cg * Dd + k];
    }
    float sqc = g_sq[cg];
    float p = *p_ptr;
    float c1 = 1.0f - p;
    __syncthreads();

    float acc[HIDh];
    #pragma unroll
    for (int h = 0; h < HIDh; h++) acc[h] = 0.0f;

    #pragma unroll 2
    for (int t = 0; t < JT / 16; t++) {
        int j = s + 16 * t;
        float dx = 0.0f, de = 0.0f;
        #pragma unroll
        for (int k = 0; k < Dd; k++) {
            dx += xc[k] * sx[j * Dd + k];
            de += ec[k] * se[j * Dd + k];
        }
        int jg = j0 + j;
        float a;
        if (jg == cg) {
            a = 1.0f;
        } else {
            float denom = c1 * (sqc + ssq[j] - 2.0f * dx) + p * de;
            a = (float)Dd / denom;
        }
        #pragma unroll
        for (int h = 0; h < HIDh; h++) acc[h] += a * sg[j * 33 + h];
    }

    // reduce over the 16 j-slots (lanes 0-15 / 16-31 of each warp)
    #pragma unroll
    for (int h = 0; h < HIDh; h++) {
        acc[h] += __shfl_down_sync(0xffffffffu, acc[h], 8);
        acc[h] += __shfl_down_sync(0xffffffffu, acc[h], 4);
        acc[h] += __shfl_down_sync(0xffffffffu, acc[h], 2);
        acc[h] += __shfl_down_sync(0xffffffffu, acc[h], 1);
    }
    if (s == 0) {
        int c = it * IT + ci;
        #pragma unroll
        for (int h = 0; h < HIDh; h++)
            g_partial[(jt * NCc + c) * HIDh + h] = acc[h];
    }
}

// ============================================================
// K4: reduce partials -> emb (sigmoid(out MLP)) -> group_embedding (output)
//     -> gelu/imp chain -> scores.
// grid = NCc (one block per center), block = 32 (thread = hidden unit h).
// Reduction loads are coalesced (one 128B line per jt per block); MLP
// stages run cooperatively via shared memory.
// ============================================================
__global__ void k4_emb(const float* __restrict__ gcn_b,
                       const float* __restrict__ out_w,
                       const float* __restrict__ out_b,
                       const float* __restrict__ w1,
                       const float* __restrict__ b1,
                       const float* __restrict__ w2,
                       const float* __restrict__ b2,
                       float* __restrict__ out) {
    int c = blockIdx.x;
    int h = threadIdx.x;

    // Reduce 34 partial tiles; keep adds in fixed (jt ascending) order for
    // determinism. Unroll so the independent loads pipeline (MLP hides lat).
    float eh = gcn_b[h];
    const float* pp = &g_partial[c * HIDh + h];
    #pragma unroll
    for (int jt = 0; jt < NJT; jt++)
        eh += pp[(size_t)jt * (NCc * HIDh)];

    __shared__ float seh[HIDh];
    __shared__ float semb[Dd];
    __shared__ float shq[SQq];
    seh[h] = eh;
    __syncwarp();

    if (h < Dd) {
        float v = out_b[h];
        #pragma unroll
        for (int q = 0; q < HIDh; q++) v += seh[q] * out_w[q * Dd + h];
        v = 1.0f / (1.0f + expf(-v));
        semb[h] = v;
        g_ge[c * Dd + h] = v;
        out[OUT_GE + c * Dd + h] = v;
    }
    __syncwarp();

    if (h < SQq) {
        float v = b1[h];
        #pragma unroll
        for (int k = 0; k < Dd; k++) v += semb[k] * w1[k * SQq + h];
        shq[h] = 0.5f * v * (1.0f + erff(v * 0.70710678118654752f));  // exact gelu
    }
    __syncwarp();

    if (h < Dd) {
        float v = b2[h];
        #pragma unroll
        for (int q = 0; q < SQq; q++) v += shq[q] * w2[q * Dd + h];
        g_sc[c * Dd + h] = 1.0f / (1.0f + expf(-v));
    }
}

// ============================================================
// K5: per-patient argmin of denom over 256 centers (== argmax of sim, with
// first-index tie-break via packed key) + gather of outputs.
// grid = Bp/32, block = 256 (8 lanes per patient)
// ============================================================
__global__ void k5_gather(const float* __restrict__ p_ptr,
                          float* __restrict__ out) {
    __shared__ float scx[NCc * Dd];
    __shared__ float sce[NCc * Dd];
    __shared__ float scsq[NCc];
    int tid = threadIdx.x;
    for (int i = tid; i < NCc * Dd; i += 256) {
        scx[i] = g_x_all[Bp * Dd + i];
        sce[i] = g_e[Bp * Dd + i];
    }
    if (tid < NCc) scsq[tid] = g_sq[Bp + tid];
    float p = *p_ptr;
    float c1 = 1.0f - p;
    __syncthreads();

    int pl = tid >> 3, l8 = tid & 7;
    int jp = blockIdx.x * 32 + pl;

    float xp[Dd], ep[Dd];
    #pragma unroll
    for (int k = 0; k < Dd; k++) {
        xp[k] = g_x_all[jp * Dd + k];
        ep[k] = g_e[jp * Dd + k];
    }
    float sqp = g_sq[jp];

    unsigned long long best = 0xFFFFFFFFFFFFFFFFull;
    for (int c = l8; c < NCc; c += 8) {
        float dx = 0.0f, de = 0.0f;
        #pragma unroll
        for (int k = 0; k < Dd; k++) {
            dx += xp[k] * scx[c * Dd + k];
            de += ep[k] * sce[c * Dd + k];
        }
        float denom = c1 * (sqp + scsq[c] - 2.0f * dx) + p * de;
        unsigned long long key =
            (((unsigned long long)__float_as_uint(denom)) << 32) | (unsigned)c;
        if (key < best) best = key;
    }
    unsigned long long o;
    o = __shfl_xor_sync(0xffffffffu, best, 1); if (o < best) best = o;
    o = __shfl_xor_sync(0xffffffffu, best, 2); if (o < best) best = o;
    o = __shfl_xor_sync(0xffffffffu, best, 4); if (o < best) best = o;

    int label = (int)(unsigned)(best & 0xFFFFFFFFull);
    for (int k = l8; k < Dd; k += 8) {
        out[OUT_GS + jp * Dd + k] = g_sc[label * Dd + k];
        out[OUT_GPE + jp * Dd + k] = g_ge[label * Dd + k];
    }
    if (l8 == 0) out[OUT_GL + jp] = (float)label;
}

// ============================================================
extern "C" void kernel_launch(void* const* d_in, const int* in_sizes, int n_in,
                              void* d_out, int out_size) {
    const float* x        = (const float*)d_in[0];
    const float* dc       = (const float*)d_in[1];
    const float* centers  = (const float*)d_in[2];
    const float* proj_w   = (const float*)d_in[3];
    const float* proj_b   = (const float*)d_in[4];
    const float* dc_param = (const float*)d_in[5];
    const float* cc       = (const float*)d_in[6];
    const float* gcn_w    = (const float*)d_in[7];
    const float* gcn_b    = (const float*)d_in[8];
    const float* out_w    = (const float*)d_in[9];
    const float* out_b    = (const float*)d_in[10];
    const float* w1       = (const float*)d_in[11];
    const float* b1       = (const float*)d_in[12];
    const float* w2       = (const float*)d_in[13];
    const float* b2       = (const float*)d_in[14];
    float* out = (float*)d_out;

    k1_patients<<<Bp, 128>>>(x, dc, gcn_w);
    k2_centers<<<1, 256>>>(centers, proj_w, proj_b, cc, gcn_w);
    k3_main<<<dim3(NJT, NIT), 256>>>(dc_param);
    k4_emb<<<NCc, 32>>>(gcn_b, out_w, out_b, w1, b1, w2, b2, out);
    k5_gather<<<Bp / 32, 256>>>(dc_param, out);
}

// round 3
// speedup vs baseline: 2.2681x; 1.3616x over previous
#include <cuda_runtime.h>
#include <cstdint>
#include <math.h>

// Problem constants
#define Bp   4096
#define Dd   19
#define Ff   64
#define NCc  256
#define HIDh 32
#define SQq  16
#define Nn   (Bp + NCc)
#define PD   20            // padded row stride (19 + 1 zero pad), float4-able
#define PD4  5             // PD/4

// K3 tiling
#define JT   128            // j per tile
#define NJT  (Nn / JT)      // 34
#define IT   16             // centers per block (8 thread-pairs x 2)
#define NIT  (NCc / IT)     // 16

// Output offsets (floats)
#define OUT_GS  0
#define OUT_GE  (Bp * Dd)
#define OUT_GPE ((Bp + NCc) * Dd)
#define OUT_GL  (((2 * Bp) + NCc) * Dd)

// -------- device scratch (no allocations allowed) --------
__device__ float4 g_x4[Nn * PD4];          // x_all rows, padded, pad = 0
__device__ float4 g_e4[Nn * PD4];          // e rows, padded, pad = 0
__device__ float  g_sq[Nn];
__device__ float4 g_g4[Nn * (HIDh / 4)];   // g = x_all @ gcn_w
__device__ float  g_partial[NJT * NCc * HIDh];
__device__ float  g_ge[NCc * Dd];
__device__ float  g_sc[NCc * Dd];

__device__ __forceinline__ float dot4(float4 a, float4 b) {
    return a.x * b.x + a.y * b.y + a.z * b.z + a.w * b.w;
}

// ============================================================
// K1: blocks 0..2047: two patients each (x_avg, e, sq, g).
//     block 2048: all 256 centers (proj + e + sq + g).
// block = 256
// ============================================================
__global__ void k1_prep(const float* __restrict__ x,
                        const float* __restrict__ dc,
                        const float* __restrict__ gcn_w,
                        const float* __restrict__ centers,
                        const float* __restrict__ proj_w,
                        const float* __restrict__ proj_b,
                        const float* __restrict__ cc) {
    __shared__ float sxa[2][PD];
    __shared__ float sw[Dd * HIDh];
    __shared__ float spw[61 * Dd];
    __shared__ float spb[Dd];
    int tid = threadIdx.x;
    float* gx = (float*)g_x4;
    float* ge = (float*)g_e4;
    float* gg = (float*)g_g4;

    if (blockIdx.x < Bp / 2) {
        // ---- patients ----
        for (int i = tid; i < Dd * HIDh; i += 256) sw[i] = gcn_w[i];

        int ps   = tid >> 7;                 // patient slot 0/1
        int t128 = tid & 127;
        int wp   = (t128 >> 5);              // warp-in-patient 0..3
        int lane = tid & 31;
        int b = blockIdx.x * 2 + ps;

        const float* xb = x + (size_t)b * (Dd * Ff);
        for (int d = wp; d < Dd; d += 4) {
            float v = xb[d * Ff + lane] + xb[d * Ff + lane + 32];
            v += __shfl_down_sync(0xffffffffu, v, 16);
            v += __shfl_down_sync(0xffffffffu, v, 8);
            v += __shfl_down_sync(0xffffffffu, v, 4);
            v += __shfl_down_sync(0xffffffffu, v, 2);
            v += __shfl_down_sync(0xffffffffu, v, 1);
            if (lane == 0) sxa[ps][d] = v * (1.0f / 64.0f);
        }
        __syncthreads();

        if (t128 < PD) {
            int k = t128;
            float xa = (k < Dd) ? sxa[ps][k] : 0.0f;
            gx[b * PD + k] = xa;
            ge[b * PD + k] = (k < Dd) ? expf(1.0f - dc[b * Dd + k]) : 0.0f;
        }
        if (t128 == 32) {
            float s = 0.0f;
            #pragma unroll
            for (int k = 0; k < Dd; k++) s += sxa[ps][k] * sxa[ps][k];
            g_sq[b] = s;
        }
        if (t128 >= 64 && t128 < 64 + HIDh) {
            int h = t128 - 64;
            float acc = 0.0f;
            #pragma unroll
            for (int k = 0; k < Dd; k++) acc += sxa[ps][k] * sw[k * HIDh + h];
            gg[b * HIDh + h] = acc;
        }
    } else {
        // ---- centers (one block, thread c = center) ----
        for (int i = tid; i < 61 * Dd; i += 256) spw[i] = proj_w[i];
        if (tid < Dd) spb[tid] = proj_b[tid];
        for (int i = tid; i < Dd * HIDh; i += 256) sw[i] = gcn_w[i];
        __syncthreads();

        int c = tid;
        float cp[Dd];
        #pragma unroll
        for (int k = 0; k < Dd; k++) cp[k] = spb[k];
        for (int m = 0; m < 61; m++) {
            float cm = centers[c * 61 + m];
            #pragma unroll
            for (int k = 0; k < Dd; k++) cp[k] += cm * spw[m * Dd + k];
        }
        int row = Bp + c;
        float s = 0.0f;
        #pragma unroll
        for (int k = 0; k < Dd; k++) {
            gx[row * PD + k] = cp[k];
            s += cp[k] * cp[k];
            ge[row * PD + k] = expf(1.0f - cc[c * Dd + k]);
        }
        gx[row * PD + Dd] = 0.0f;
        ge[row * PD + Dd] = 0.0f;
        g_sq[row] = s;
        #pragma unroll
        for (int h = 0; h < HIDh; h++) {
            float acc = 0.0f;
            #pragma unroll
            for (int k = 0; k < Dd; k++) acc += cp[k] * sw[k * HIDh + h];
            gg[row * HIDh + h] = acc;
        }
    }
}

// ============================================================
// K3: fused adjacency + adj@g for center rows. CB=2 register blocking.
// grid = (NJT, NIT), block = 256: thread = (cp 0..7, s 0..31).
// Each thread: 2 centers in registers, 4 j's; butterfly reduce over lanes.
// ============================================================
__global__ void __launch_bounds__(256, 1) k3_main(const float* __restrict__ p_ptr) {
    __shared__ float4 sx4[JT * PD4];
    __shared__ float4 se4[JT * PD4];
    __shared__ float  sg[JT * 33];   // stride-33 pad: conflict-free j-gather
    __shared__ float  ssq[JT];

    int tid = threadIdx.x;
    int jt = blockIdx.x, it = blockIdx.y;
    int j0 = jt * JT;

    for (int i = tid; i < JT * PD4; i += 256) {
        sx4[i] = g_x4[j0 * PD4 + i];
        se4[i] = g_e4[j0 * PD4 + i];
    }
    for (int i = tid; i < JT * (HIDh / 4); i += 256) {
        int j = i >> 3, q = i & 7;
        float4 gv = g_g4[(size_t)(j0 + j) * (HIDh / 4) + q];
        sg[j * 33 + q * 4 + 0] = gv.x;
        sg[j * 33 + q * 4 + 1] = gv.y;
        sg[j * 33 + q * 4 + 2] = gv.z;
        sg[j * 33 + q * 4 + 3] = gv.w;
    }
    if (tid < JT) ssq[tid] = g_sq[j0 + tid];

    int cp = tid >> 5, s = tid & 31;
    int cA = it * IT + cp * 2;
    int cB = cA + 1;
    int cgA = Bp + cA, cgB = Bp + cB;

    float4 xA[PD4], eA[PD4], xB[PD4], eB[PD4];
    #pragma unroll
    for (int q = 0; q < PD4; q++) {
        xA[q] = g_x4[cgA * PD4 + q];
        eA[q] = g_e4[cgA * PD4 + q];
        xB[q] = g_x4[cgB * PD4 + q];
        eB[q] = g_e4[cgB * PD4 + q];
    }
    float sqA = g_sq[cgA], sqB = g_sq[cgB];
    float p = *p_ptr;
    float c1 = 1.0f - p;
    __syncthreads();

    float accA[HIDh], accB[HIDh];
    #pragma unroll
    for (int h = 0; h < HIDh; h++) { accA[h] = 0.0f; accB[h] = 0.0f; }

    #pragma unroll
    for (int t = 0; t < JT / 32; t++) {
        int j = s + 32 * t;
        float dxA = 0.0f, deA = 0.0f, dxB = 0.0f, deB = 0.0f;
        #pragma unroll
        for (int q = 0; q < PD4; q++) {
            float4 v = sx4[j * PD4 + q];
            float4 w = se4[j * PD4 + q];
            dxA += dot4(xA[q], v);  deA += dot4(eA[q], w);
            dxB += dot4(xB[q], v);  deB += dot4(eB[q], w);
        }
        int jg = j0 + j;
        float aA = (jg == cgA) ? 1.0f
                 : (float)Dd / (c1 * (sqA + ssq[j] - 2.0f * dxA) + p * deA);
        float aB = (jg == cgB) ? 1.0f
                 : (float)Dd / (c1 * (sqB + ssq[j] - 2.0f * dxB) + p * deB);
        #pragma unroll
        for (int h = 0; h < HIDh; h++) {
            float gv = sg[j * 33 + h];
            accA[h] += aA * gv;
            accB[h] += aB * gv;
        }
    }

    // Distributed butterfly reduction over the 32 lanes: after it,
    // lane s holds the lane-sum for h = s in acc[0..? folded].
    #pragma unroll
    for (int d = 16; d >= 1; d >>= 1) {
        #pragma unroll
        for (int i = 0; i < d; i++) {
            float sendA = (s & d) ? accA[i] : accA[i + d];
            float sendB = (s & d) ? accB[i] : accB[i + d];
            float recvA = __shfl_xor_sync(0xffffffffu, sendA, d);
            float recvB = __shfl_xor_sync(0xffffffffu, sendB, d);
            accA[i] = ((s & d) ? accA[i + d] : accA[i]) + recvA;
            accB[i] = ((s & d) ? accB[i + d] : accB[i]) + recvB;
        }
    }
    g_partial[((size_t)jt * NCc + cA) * HIDh + s] = accA[0];
    g_partial[((size_t)jt * NCc + cB) * HIDh + s] = accB[0];
}

// ============================================================
// K4: reduce partials (4 warps) -> sigmoid MLP -> group_embedding ->
//     gelu/imp chain -> scores.  grid = NCc, block = 128.
// ============================================================
__global__ void k4_emb(const float* __restrict__ gcn_b,
                       const float* __restrict__ out_w,
                       const float* __restrict__ out_b,
                       const float* __restrict__ w1,
                       const float* __restrict__ b1,
                       const float* __restrict__ w2,
                       const float* __restrict__ b2,
                       float* __restrict__ out) {
    __shared__ float sp[4 * HIDh];
    __shared__ float seh[HIDh];
    __shared__ float semb[Dd];
    __shared__ float shq[SQq];

    int c = blockIdx.x;
    int w = threadIdx.x >> 5;
    int h = threadIdx.x & 31;

    // warp w sums jt in [w*9, min(34, w*9+9)); ascending, deterministic.
    int jt0 = w * 9;
    int jt1 = (w == 3) ? NJT : jt0 + 9;
    float ps = 0.0f;
    const float* pp = &g_partial[(size_t)c * HIDh + h];
    #pragma unroll 9
    for (int jt = jt0; jt < jt1; jt++)
        ps += pp[(size_t)jt * (NCc * HIDh)];
    sp[w * HIDh + h] = ps;
    __syncthreads();

    if (w == 0) {
        float eh = gcn_b[h] + sp[h] + sp[HIDh + h] + sp[2 * HIDh + h] + sp[3 * HIDh + h];
        seh[h] = eh;
        __syncwarp();

        if (h < Dd) {
            float v = out_b[h];
            #pragma unroll
            for (int q = 0; q < HIDh; q++) v += seh[q] * out_w[q * Dd + h];
            v = 1.0f / (1.0f + expf(-v));
            semb[h] = v;
            g_ge[c * Dd + h] = v;
            out[OUT_GE + c * Dd + h] = v;
        }
        __syncwarp();

        if (h < SQq) {
            float v = b1[h];
            #pragma unroll
            for (int k = 0; k < Dd; k++) v += semb[k] * w1[k * SQq + h];
            shq[h] = 0.5f * v * (1.0f + erff(v * 0.70710678118654752f));
        }
        __syncwarp();

        if (h < Dd) {
            float v = b2[h];
            #pragma unroll
            for (int q = 0; q < SQq; q++) v += shq[q] * w2[q * Dd + h];
            g_sc[c * Dd + h] = 1.0f / (1.0f + expf(-v));
        }
    }
}

// ============================================================
// K5: per-patient argmin of denom over 256 centers (== argmax sim,
// first-index tie-break) + gather.  PB=2 patient blocking.
// grid = 128, block = 128: thread = (pair 0..15, l8 0..7), 32 patients/block.
// ============================================================
__global__ void k5_gather(const float* __restrict__ p_ptr,
                          float* __restrict__ out) {
    __shared__ float4 scx4[NCc * PD4];
    __shared__ float4 sce4[NCc * PD4];
    __shared__ float  scsq[NCc];
    int tid = threadIdx.x;
    for (int i = tid; i < NCc * PD4; i += 128) {
        scx4[i] = g_x4[Bp * PD4 + i];
        sce4[i] = g_e4[Bp * PD4 + i];
    }
    for (int i = tid; i < NCc; i += 128) scsq[i] = g_sq[Bp + i];
    float p = *p_ptr;
    float c1 = 1.0f - p;
    __syncthreads();

    int pr = tid >> 3, l8 = tid & 7;
    int jp0 = blockIdx.x * 32 + pr * 2;
    int jp1 = jp0 + 1;

    float4 x0[PD4], e0[PD4], x1[PD4], e1[PD4];
    #pragma unroll
    for (int q = 0; q < PD4; q++) {
        x0[q] = g_x4[jp0 * PD4 + q];
        e0[q] = g_e4[jp0 * PD4 + q];
        x1[q] = g_x4[jp1 * PD4 + q];
        e1[q] = g_e4[jp1 * PD4 + q];
    }
    float sq0 = g_sq[jp0], sq1 = g_sq[jp1];

    unsigned long long best0 = 0xFFFFFFFFFFFFFFFFull;
    unsigned long long best1 = 0xFFFFFFFFFFFFFFFFull;
    #pragma unroll 4
    for (int c = l8; c < NCc; c += 8) {
        float dx0 = 0.0f, de0 = 0.0f, dx1 = 0.0f, de1 = 0.0f;
        #pragma unroll
        for (int q = 0; q < PD4; q++) {
            float4 v = scx4[c * PD4 + q];
            float4 w = sce4[c * PD4 + q];
            dx0 += dot4(x0[q], v);  de0 += dot4(e0[q], w);
            dx1 += dot4(x1[q], v);  de1 += dot4(e1[q], w);
        }
        float den0 = c1 * (sq0 + scsq[c] - 2.0f * dx0) + p * de0;
        float den1 = c1 * (sq1 + scsq[c] - 2.0f * dx1) + p * de1;
        unsigned long long k0 =
            (((unsigned long long)__float_as_uint(den0)) << 32) | (unsigned)c;
        unsigned long long k1 =
            (((unsigned long long)__float_as_uint(den1)) << 32) | (unsigned)c;
        if (k0 < best0) best0 = k0;
        if (k1 < best1) best1 = k1;
    }
    unsigned long long o;
    o = __shfl_xor_sync(0xffffffffu, best0, 1); if (o < best0) best0 = o;
    o = __shfl_xor_sync(0xffffffffu, best0, 2); if (o < best0) best0 = o;
    o = __shfl_xor_sync(0xffffffffu, best0, 4); if (o < best0) best0 = o;
    o = __shfl_xor_sync(0xffffffffu, best1, 1); if (o < best1) best1 = o;
    o = __shfl_xor_sync(0xffffffffu, best1, 2); if (o < best1) best1 = o;
    o = __shfl_xor_sync(0xffffffffu, best1, 4); if (o < best1) best1 = o;

    int lab0 = (int)(unsigned)(best0 & 0xFFFFFFFFull);
    int lab1 = (int)(unsigned)(best1 & 0xFFFFFFFFull);
    for (int k = l8; k < Dd; k += 8) {
        out[OUT_GS + jp0 * Dd + k]  = g_sc[lab0 * Dd + k];
        out[OUT_GPE + jp0 * Dd + k] = g_ge[lab0 * Dd + k];
        out[OUT_GS + jp1 * Dd + k]  = g_sc[lab1 * Dd + k];
        out[OUT_GPE + jp1 * Dd + k] = g_ge[lab1 * Dd + k];
    }
    if (l8 == 0) {
        out[OUT_GL + jp0] = (float)lab0;
        out[OUT_GL + jp1] = (float)lab1;
    }
}

// ============================================================
extern "C" void kernel_launch(void* const* d_in, const int* in_sizes, int n_in,
                              void* d_out, int out_size) {
    const float* x        = (const float*)d_in[0];
    const float* dc       = (const float*)d_in[1];
    const float* centers  = (const float*)d_in[2];
    const float* proj_w   = (const float*)d_in[3];
    const float* proj_b   = (const float*)d_in[4];
    const float* dc_param = (const float*)d_in[5];
    const float* cc       = (const float*)d_in[6];
    const float* gcn_w    = (const float*)d_in[7];
    const float* gcn_b    = (const float*)d_in[8];
    const float* out_w    = (const float*)d_in[9];
    const float* out_b    = (const float*)d_in[10];
    const float* w1       = (const float*)d_in[11];
    const float* b1       = (const float*)d_in[12];
    const float* w2       = (const float*)d_in[13];
    const float* b2       = (const float*)d_in[14];
    float* out = (float*)d_out;

    k1_prep<<<Bp / 2 + 1, 256>>>(x, dc, gcn_w, centers, proj_w, proj_b, cc);
    k3_main<<<dim3(NJT, NIT), 256>>>(dc_param);
    k4_emb<<<NCc, 128>>>(gcn_b, out_w, out_b, w1, b1, w2, b2, out);
    k5_gather<<<128, 128>>>(dc_param, out);
}

// round 4
// speedup vs baseline: 2.5960x; 1.1446x over previous
#include <cuda_runtime.h>
#include <cstdint>
#include <math.h>

// Problem constants
#define Bp   4096
#define Dd   19
#define Ff   64
#define NCc  256
#define HIDh 32
#define SQq  16
#define Nn   (Bp + NCc)
#define PD   20            // padded row stride (19 + 1 zero pad), float4-able
#define PD4  5             // PD/4

// K3 tiling
#define JT   128            // j per tile
#define NJT  (Nn / JT)      // 34
#define NPJT (Bp / JT)      // 32 patient-only tiles
#define IT   16             // centers per block (8 thread-pairs x 2)
#define NIT  (NCc / IT)     // 16

// Output offsets (floats)
#define OUT_GS  0
#define OUT_GE  (Bp * Dd)
#define OUT_GPE ((Bp + NCc) * Dd)
#define OUT_GL  (((2 * Bp) + NCc) * Dd)

// -------- device scratch (no allocations allowed) --------
__device__ float4 g_x4[Nn * PD4];          // x_all rows, padded, pad = 0
__device__ float4 g_e4[Nn * PD4];          // e rows, padded, pad = 0
__device__ float  g_sq[Nn];
__device__ float4 g_g4[Nn * (HIDh / 4)];   // g = x_all @ gcn_w
__device__ float  g_partial[NJT * NCc * HIDh];
__device__ unsigned long long g_key[NIT * Bp];  // per (center-tile, patient) argmin key
__device__ float  g_ge[NCc * Dd];
__device__ float  g_sc[NCc * Dd];

__device__ __forceinline__ float dot4(float4 a, float4 b) {
    return a.x * b.x + a.y * b.y + a.z * b.z + a.w * b.w;
}

// ============================================================
// K1: blocks 0..2047: two patients each (x_avg, e, sq, g).
//     block 2048: all 256 centers (proj + e + sq + g).
// block = 256
// ============================================================
__global__ void k1_prep(const float* __restrict__ x,
                        const float* __restrict__ dc,
                        const float* __restrict__ gcn_w,
                        const float* __restrict__ centers,
                        const float* __restrict__ proj_w,
                        const float* __restrict__ proj_b,
                        const float* __restrict__ cc) {
    __shared__ float sxa[2][PD];
    __shared__ float sw[Dd * HIDh];
    __shared__ float spw[61 * Dd];
    __shared__ float spb[Dd];
    int tid = threadIdx.x;
    float* gx = (float*)g_x4;
    float* ge = (float*)g_e4;
    float* gg = (float*)g_g4;

    if (blockIdx.x < Bp / 2) {
        // ---- patients ----
        for (int i = tid; i < Dd * HIDh; i += 256) sw[i] = gcn_w[i];

        int ps   = tid >> 7;                 // patient slot 0/1
        int t128 = tid & 127;
        int wp   = (t128 >> 5);              // warp-in-patient 0..3
        int lane = tid & 31;
        int b = blockIdx.x * 2 + ps;

        const float* xb = x + (size_t)b * (Dd * Ff);
        for (int d = wp; d < Dd; d += 4) {
            float v = xb[d * Ff + lane] + xb[d * Ff + lane + 32];
            v += __shfl_down_sync(0xffffffffu, v, 16);
            v += __shfl_down_sync(0xffffffffu, v, 8);
            v += __shfl_down_sync(0xffffffffu, v, 4);
            v += __shfl_down_sync(0xffffffffu, v, 2);
            v += __shfl_down_sync(0xffffffffu, v, 1);
            if (lane == 0) sxa[ps][d] = v * (1.0f / 64.0f);
        }
        __syncthreads();

        if (t128 < PD) {
            int k = t128;
            float xa = (k < Dd) ? sxa[ps][k] : 0.0f;
            gx[b * PD + k] = xa;
            ge[b * PD + k] = (k < Dd) ? expf(1.0f - dc[b * Dd + k]) : 0.0f;
        }
        if (t128 == 32) {
            float s = 0.0f;
            #pragma unroll
            for (int k = 0; k < Dd; k++) s += sxa[ps][k] * sxa[ps][k];
            g_sq[b] = s;
        }
        if (t128 >= 64 && t128 < 64 + HIDh) {
            int h = t128 - 64;
            float acc = 0.0f;
            #pragma unroll
            for (int k = 0; k < Dd; k++) acc += sxa[ps][k] * sw[k * HIDh + h];
            gg[b * HIDh + h] = acc;
        }
    } else {
        // ---- centers (one block, thread c = center) ----
        for (int i = tid; i < 61 * Dd; i += 256) spw[i] = proj_w[i];
        if (tid < Dd) spb[tid] = proj_b[tid];
        for (int i = tid; i < Dd * HIDh; i += 256) sw[i] = gcn_w[i];
        __syncthreads();

        int c = tid;
        float cp[Dd];
        #pragma unroll
        for (int k = 0; k < Dd; k++) cp[k] = spb[k];
        for (int m = 0; m < 61; m++) {
            float cm = centers[c * 61 + m];
            #pragma unroll
            for (int k = 0; k < Dd; k++) cp[k] += cm * spw[m * Dd + k];
        }
        int row = Bp + c;
        float s = 0.0f;
        #pragma unroll
        for (int k = 0; k < Dd; k++) {
            gx[row * PD + k] = cp[k];
            s += cp[k] * cp[k];
            ge[row * PD + k] = expf(1.0f - cc[c * Dd + k]);
        }
        gx[row * PD + Dd] = 0.0f;
        ge[row * PD + Dd] = 0.0f;
        g_sq[row] = s;
        #pragma unroll
        for (int h = 0; h < HIDh; h++) {
            float acc = 0.0f;
            #pragma unroll
            for (int k = 0; k < Dd; k++) acc += cp[k] * sw[k * HIDh + h];
            gg[row * HIDh + h] = acc;
        }
    }
}

// ============================================================
// K3: fused adjacency + adj@g for center rows, CB=2 register blocking,
//     PLUS per-(patient, center-tile) argmin-denominator key emission
//     (the group_label argmax is a byproduct of work already done here).
// grid = (NJT, NIT), block = 256: thread = (cp 0..7, s 0..31).
// ============================================================
__global__ void __launch_bounds__(256, 1) k3_main(const float* __restrict__ p_ptr) {
    __shared__ float4 sx4[JT * PD4];
    __shared__ float4 se4[JT * PD4];
    __shared__ float  sg[JT * 33];   // stride-33 pad: conflict-free j-gather
    __shared__ float  ssq[JT];
    __shared__ unsigned long long skey[8][JT + 1];  // [cp][j], +1 pad

    int tid = threadIdx.x;
    int jt = blockIdx.x, it = blockIdx.y;
    int j0 = jt * JT;
    bool patient_tile = (jt < NPJT);

    for (int i = tid; i < JT * PD4; i += 256) {
        sx4[i] = g_x4[j0 * PD4 + i];
        se4[i] = g_e4[j0 * PD4 + i];
    }
    for (int i = tid; i < JT * (HIDh / 4); i += 256) {
        int j = i >> 3, q = i & 7;
        float4 gv = g_g4[(size_t)(j0 + j) * (HIDh / 4) + q];
        sg[j * 33 + q * 4 + 0] = gv.x;
        sg[j * 33 + q * 4 + 1] = gv.y;
        sg[j * 33 + q * 4 + 2] = gv.z;
        sg[j * 33 + q * 4 + 3] = gv.w;
    }
    if (tid < JT) ssq[tid] = g_sq[j0 + tid];

    int cp = tid >> 5, s = tid & 31;
    int cA = it * IT + cp * 2;
    int cB = cA + 1;
    int cgA = Bp + cA, cgB = Bp + cB;

    float4 xA[PD4], eA[PD4], xB[PD4], eB[PD4];
    #pragma unroll
    for (int q = 0; q < PD4; q++) {
        xA[q] = g_x4[cgA * PD4 + q];
        eA[q] = g_e4[cgA * PD4 + q];
        xB[q] = g_x4[cgB * PD4 + q];
        eB[q] = g_e4[cgB * PD4 + q];
    }
    float sqA = g_sq[cgA], sqB = g_sq[cgB];
    float p = *p_ptr;
    float c1 = 1.0f - p;
    __syncthreads();

    float accA[HIDh], accB[HIDh];
    #pragma unroll
    for (int h = 0; h < HIDh; h++) { accA[h] = 0.0f; accB[h] = 0.0f; }

    #pragma unroll
    for (int t = 0; t < JT / 32; t++) {
        int j = s + 32 * t;
        float dxA = 0.0f, deA = 0.0f, dxB = 0.0f, deB = 0.0f;
        #pragma unroll
        for (int q = 0; q < PD4; q++) {
            float4 v = sx4[j * PD4 + q];
            float4 w = se4[j * PD4 + q];
            dxA += dot4(xA[q], v);  deA += dot4(eA[q], w);
            dxB += dot4(xB[q], v);  deB += dot4(eB[q], w);
        }
        int jg = j0 + j;
        float denA = c1 * (sqA + ssq[j] - 2.0f * dxA) + p * deA;
        float denB = c1 * (sqB + ssq[j] - 2.0f * dxB) + p * deB;
        float aA = (jg == cgA) ? 1.0f : (float)Dd / denA;
        float aB = (jg == cgB) ? 1.0f : (float)Dd / denB;

        if (patient_tile) {
            // argmin-denominator key (== argmax sim, first-index tie-break)
            unsigned long long kA =
                (((unsigned long long)__float_as_uint(denA)) << 32) | (unsigned)cA;
            unsigned long long kB =
                (((unsigned long long)__float_as_uint(denB)) << 32) | (unsigned)cB;
            skey[cp][j] = (kA < kB) ? kA : kB;
        }

        #pragma unroll
        for (int h = 0; h < HIDh; h++) {
            float gv = sg[j * 33 + h];
            accA[h] += aA * gv;
            accB[h] += aB * gv;
        }
    }

    if (patient_tile) {
        __syncthreads();
        if (tid < JT) {
            unsigned long long m = skey[0][tid];
            #pragma unroll
            for (int q = 1; q < 8; q++) {
                unsigned long long v = skey[q][tid];
                if (v < m) m = v;
            }
            g_key[(size_t)it * Bp + j0 + tid] = m;
        }
    }

    // Distributed butterfly reduction over the 32 lanes: lane s ends
    // holding the lane-sum for h = s in acc[0].
    #pragma unroll
    for (int d = 16; d >= 1; d >>= 1) {
        #pragma unroll
        for (int i = 0; i < d; i++) {
            float sendA = (s & d) ? accA[i] : accA[i + d];
            float sendB = (s & d) ? accB[i] : accB[i + d];
            float recvA = __shfl_xor_sync(0xffffffffu, sendA, d);
            float recvB = __shfl_xor_sync(0xffffffffu, sendB, d);
            accA[i] = ((s & d) ? accA[i + d] : accA[i]) + recvA;
            accB[i] = ((s & d) ? accB[i + d] : accB[i]) + recvB;
        }
    }
    g_partial[((size_t)jt * NCc + cA) * HIDh + s] = accA[0];
    g_partial[((size_t)jt * NCc + cB) * HIDh + s] = accB[0];
}

// ============================================================
// K4: reduce partials (4 warps) -> sigmoid MLP -> group_embedding ->
//     gelu/imp chain -> scores.  grid = NCc, block = 128.
// ============================================================
__global__ void k4_emb(const float* __restrict__ gcn_b,
                       const float* __restrict__ out_w,
                       const float* __restrict__ out_b,
                       const float* __restrict__ w1,
                       const float* __restrict__ b1,
                       const float* __restrict__ w2,
                       const float* __restrict__ b2,
                       float* __restrict__ out) {
    __shared__ float sp[4 * HIDh];
    __shared__ float seh[HIDh];
    __shared__ float semb[Dd];
    __shared__ float shq[SQq];

    int c = blockIdx.x;
    int w = threadIdx.x >> 5;
    int h = threadIdx.x & 31;

    // warp w sums jt in [w*9, min(34, w*9+9)); ascending, deterministic.
    int jt0 = w * 9;
    int jt1 = (w == 3) ? NJT : jt0 + 9;
    float ps = 0.0f;
    const float* pp = &g_partial[(size_t)c * HIDh + h];
    #pragma unroll 9
    for (int jt = jt0; jt < jt1; jt++)
        ps += pp[(size_t)jt * (NCc * HIDh)];
    sp[w * HIDh + h] = ps;
    __syncthreads();

    if (w == 0) {
        float eh = gcn_b[h] + sp[h] + sp[HIDh + h] + sp[2 * HIDh + h] + sp[3 * HIDh + h];
        seh[h] = eh;
        __syncwarp();

        if (h < Dd) {
            float v = out_b[h];
            #pragma unroll
            for (int q = 0; q < HIDh; q++) v += seh[q] * out_w[q * Dd + h];
            v = 1.0f / (1.0f + expf(-v));
            semb[h] = v;
            g_ge[c * Dd + h] = v;
            out[OUT_GE + c * Dd + h] = v;
        }
        __syncwarp();

        if (h < SQq) {
            float v = b1[h];
            #pragma unroll
            for (int k = 0; k < Dd; k++) v += semb[k] * w1[k * SQq + h];
            shq[h] = 0.5f * v * (1.0f + erff(v * 0.70710678118654752f));
        }
        __syncwarp();

        if (h < Dd) {
            float v = b2[h];
            #pragma unroll
            for (int q = 0; q < SQq; q++) v += shq[q] * w2[q * Dd + h];
            g_sc[c * Dd + h] = 1.0f / (1.0f + expf(-v));
        }
    }
}

// ============================================================
// K5: reduce 16 per-tile keys per patient -> label; gather score/embedding
// rows. grid = 128, block = 256: 32 patients/block, 8 lanes/patient.
// ============================================================
__global__ void k5_gather(float* __restrict__ out) {
    int tid = threadIdx.x;
    int pl = tid >> 3, l8 = tid & 7;
    int jp = blockIdx.x * 32 + pl;

    unsigned long long k0 = g_key[(size_t)l8 * Bp + jp];
    unsigned long long k1 = g_key[(size_t)(l8 + 8) * Bp + jp];
    unsigned long long best = (k0 < k1) ? k0 : k1;
    unsigned long long o;
    o = __shfl_xor_sync(0xffffffffu, best, 1); if (o < best) best = o;
    o = __shfl_xor_sync(0xffffffffu, best, 2); if (o < best) best = o;
    o = __shfl_xor_sync(0xffffffffu, best, 4); if (o < best) best = o;
    // broadcast within the 8-lane group
    int lane = tid & 31;
    best = __shfl_sync(0xffffffffu, best, lane & ~7);

    int label = (int)(unsigned)(best & 0xFFFFFFFFull);
    #pragma unroll
    for (int k = l8; k < Dd; k += 8) {
        out[OUT_GS + jp * Dd + k]  = g_sc[label * Dd + k];
        out[OUT_GPE + jp * Dd + k] = g_ge[label * Dd + k];
    }
    if (l8 == 0) out[OUT_GL + jp] = (float)label;
}

// ============================================================
extern "C" void kernel_launch(void* const* d_in, const int* in_sizes, int n_in,
                              void* d_out, int out_size) {
    const float* x        = (const float*)d_in[0];
    const float* dc       = (const float*)d_in[1];
    const float* centers  = (const float*)d_in[2];
    const float* proj_w   = (const float*)d_in[3];
    const float* proj_b   = (const float*)d_in[4];
    const float* dc_param = (const float*)d_in[5];
    const float* cc       = (const float*)d_in[6];
    const float* gcn_w    = (const float*)d_in[7];
    const float* gcn_b    = (const float*)d_in[8];
    const float* out_w    = (const float*)d_in[9];
    const float* out_b    = (const float*)d_in[10];
    const float* w1       = (const float*)d_in[11];
    const float* b1       = (const float*)d_in[12];
    const float* w2       = (const float*)d_in[13];
    const float* b2       = (const float*)d_in[14];
    float* out = (float*)d_out;

    k1_prep<<<Bp / 2 + 1, 256>>>(x, dc, gcn_w, centers, proj_w, proj_b, cc);
    k3_main<<<dim3(NJT, NIT), 256>>>(dc_param);
    k4_emb<<<NCc, 128>>>(gcn_b, out_w, out_b, w1, b1, w2, b2, out);
    k5_gather<<<128, 256>>>(out);
}

// round 5
// speedup vs baseline: 2.6934x; 1.0375x over previous
#include <cuda_runtime.h>
#include <cstdint>
#include <math.h>

// Problem constants
#define Bp   4096
#define Dd   19
#define Ff   64
#define NCc  256
#define HIDh 32
#define SQq  16
#define Nn   (Bp + NCc)
#define PD   20            // padded row stride (19 + 1 zero pad), float4-able
#define PD4  5             // PD/4

// K3 tiling
#define JT   128            // j per tile
#define NJT  (Nn / JT)      // 34
#define NPJT (Bp / JT)      // 32 patient-only tiles
#define IT   16             // centers per block (8 thread-pairs x 2)
#define NIT  (NCc / IT)     // 16

// Output offsets (floats)
#define OUT_GS  0
#define OUT_GE  (Bp * Dd)
#define OUT_GPE ((Bp + NCc) * Dd)
#define OUT_GL  (((2 * Bp) + NCc) * Dd)

typedef unsigned long long u64;

// -------- device scratch (no allocations allowed) --------
__device__ float4 g_x4[Nn * PD4];          // x_all rows, padded, pad = 0
__device__ float4 g_e4[Nn * PD4];          // e rows, padded, pad = 0
__device__ float  g_sq[Nn];
__device__ float4 g_g4[Nn * (HIDh / 4)];   // g = x_all @ gcn_w
__device__ float  g_partial[NJT * NCc * HIDh];
__device__ u64    g_key[Bp * NIT];         // [patient][center-tile] argmin key
__device__ float  g_ge[NCc * Dd];
__device__ float  g_sc[NCc * Dd];

// packed f32x2 fma: d = a*b + d (FFMA2, PTX-only on sm_103a)
__device__ __forceinline__ void ffma2(u64& d, u64 a, u64 b) {
    asm("fma.rn.f32x2 %0, %1, %2, %0;" : "+l"(d) : "l"(a), "l"(b));
}
__device__ __forceinline__ float lo32(u64 v) {
    return __uint_as_float((unsigned)(v & 0xFFFFFFFFull));
}
__device__ __forceinline__ float hi32(u64 v) {
    return __uint_as_float((unsigned)(v >> 32));
}
__device__ __forceinline__ u64 pack2(float a, float b) {
    u64 r;
    asm("mov.b64 %0, {%1, %2};" : "=l"(r) : "r"(__float_as_uint(a)), "r"(__float_as_uint(b)));
    return r;
}

// ============================================================
// K1: blocks 0..2047: two patients each (x_avg, e, sq, g).
//     block 2048: all 256 centers (proj + e + sq + g).
// block = 256
// ============================================================
__global__ void k1_prep(const float* __restrict__ x,
                        const float* __restrict__ dc,
                        const float* __restrict__ gcn_w,
                        const float* __restrict__ centers,
                        const float* __restrict__ proj_w,
                        const float* __restrict__ proj_b,
                        const float* __restrict__ cc) {
    __shared__ float sxa[2][PD];
    __shared__ float sw[Dd * HIDh];
    __shared__ float spw[61 * Dd];
    __shared__ float spb[Dd];
    int tid = threadIdx.x;
    float* gx = (float*)g_x4;
    float* ge = (float*)g_e4;
    float* gg = (float*)g_g4;

    if (blockIdx.x < Bp / 2) {
        // ---- patients ----
        for (int i = tid; i < Dd * HIDh; i += 256) sw[i] = gcn_w[i];

        int ps   = tid >> 7;                 // patient slot 0/1
        int t128 = tid & 127;
        int wp   = (t128 >> 5);              // warp-in-patient 0..3
        int lane = tid & 31;
        int b = blockIdx.x * 2 + ps;

        const float* xb = x + (size_t)b * (Dd * Ff);
        for (int d = wp; d < Dd; d += 4) {
            float v = xb[d * Ff + lane] + xb[d * Ff + lane + 32];
            v += __shfl_down_sync(0xffffffffu, v, 16);
            v += __shfl_down_sync(0xffffffffu, v, 8);
            v += __shfl_down_sync(0xffffffffu, v, 4);
            v += __shfl_down_sync(0xffffffffu, v, 2);
            v += __shfl_down_sync(0xffffffffu, v, 1);
            if (lane == 0) sxa[ps][d] = v * (1.0f / 64.0f);
        }
        __syncthreads();

        if (t128 < PD) {
            int k = t128;
            float xa = (k < Dd) ? sxa[ps][k] : 0.0f;
            gx[b * PD + k] = xa;
            ge[b * PD + k] = (k < Dd) ? expf(1.0f - dc[b * Dd + k]) : 0.0f;
        }
        if (t128 == 32) {
            float s = 0.0f;
            #pragma unroll
            for (int k = 0; k < Dd; k++) s += sxa[ps][k] * sxa[ps][k];
            g_sq[b] = s;
        }
        if (t128 >= 64 && t128 < 64 + HIDh) {
            int h = t128 - 64;
            float acc = 0.0f;
            #pragma unroll
            for (int k = 0; k < Dd; k++) acc += sxa[ps][k] * sw[k * HIDh + h];
            gg[b * HIDh + h] = acc;
        }
    } else {
        // ---- centers (one block, thread c = center) ----
        for (int i = tid; i < 61 * Dd; i += 256) spw[i] = proj_w[i];
        if (tid < Dd) spb[tid] = proj_b[tid];
        for (int i = tid; i < Dd * HIDh; i += 256) sw[i] = gcn_w[i];
        __syncthreads();

        int c = tid;
        float cp[Dd];
        #pragma unroll
        for (int k = 0; k < Dd; k++) cp[k] = spb[k];
        for (int m = 0; m < 61; m++) {
            float cm = centers[c * 61 + m];
            #pragma unroll
            for (int k = 0; k < Dd; k++) cp[k] += cm * spw[m * Dd + k];
        }
        int row = Bp + c;
        float s = 0.0f;
        #pragma unroll
        for (int k = 0; k < Dd; k++) {
            gx[row * PD + k] = cp[k];
            s += cp[k] * cp[k];
            ge[row * PD + k] = expf(1.0f - cc[c * Dd + k]);
        }
        gx[row * PD + Dd] = 0.0f;
        ge[row * PD + Dd] = 0.0f;
        g_sq[row] = s;
        #pragma unroll
        for (int h = 0; h < HIDh; h++) {
            float acc = 0.0f;
            #pragma unroll
            for (int k = 0; k < Dd; k++) acc += cp[k] * sw[k * HIDh + h];
            gg[row * HIDh + h] = acc;
        }
    }
}

// ============================================================
// K3: fused adjacency + adj@g for center rows (CB=2, f32x2 packed math)
//     + per-(patient, center-tile) argmin key emission.
// grid = (NJT, NIT), block = 256: thread = (cp 0..7, s 0..31).
// ============================================================
__global__ void __launch_bounds__(256) k3_main(const float* __restrict__ p_ptr) {
    __shared__ ulonglong2 sxu[JT * PD4];      // x rows, 16B granules (f32x2 pairs)
    __shared__ ulonglong2 seu[JT * PD4];
    __shared__ u64  sg2[JT * 17];             // g rows: 16 u64 + 1 pad (stride 17)
    __shared__ float ssq[JT];
    __shared__ u64 skey[8][JT + 1];           // [cp][j], +1 pad

    int tid = threadIdx.x;
    int jt = blockIdx.x, it = blockIdx.y;
    int j0 = jt * JT;
    bool patient_tile = (jt < NPJT);

    const ulonglong2* gx = (const ulonglong2*)g_x4;
    const ulonglong2* geu = (const ulonglong2*)g_e4;
    for (int i = tid; i < JT * PD4; i += 256) {
        sxu[i] = gx[j0 * PD4 + i];
        seu[i] = geu[j0 * PD4 + i];
    }
    for (int i = tid; i < JT * (HIDh / 4); i += 256) {
        int j = i >> 3, q = i & 7;
        float4 gv = g_g4[(size_t)(j0 + j) * (HIDh / 4) + q];
        sg2[j * 17 + q * 2 + 0] = pack2(gv.x, gv.y);
        sg2[j * 17 + q * 2 + 1] = pack2(gv.z, gv.w);
    }
    if (tid < JT) ssq[tid] = g_sq[j0 + tid];

    int cp = tid >> 5, s = tid & 31;
    int cA = it * IT + cp * 2;
    int cB = cA + 1;
    int cgA = Bp + cA, cgB = Bp + cB;

    ulonglong2 xA[PD4], eA[PD4], xB[PD4], eB[PD4];
    #pragma unroll
    for (int q = 0; q < PD4; q++) {
        xA[q] = gx[cgA * PD4 + q];
        eA[q] = geu[cgA * PD4 + q];
        xB[q] = gx[cgB * PD4 + q];
        eB[q] = geu[cgB * PD4 + q];
    }
    float sqA = g_sq[cgA], sqB = g_sq[cgB];
    float p = *p_ptr;
    float c1 = 1.0f - p;
    __syncthreads();

    u64 accA[HIDh / 2], accB[HIDh / 2];
    #pragma unroll
    for (int h = 0; h < HIDh / 2; h++) { accA[h] = 0ull; accB[h] = 0ull; }

    #pragma unroll
    for (int t = 0; t < JT / 32; t++) {
        int j = s + 32 * t;
        u64 dxA2 = 0ull, deA2 = 0ull, dxB2 = 0ull, deB2 = 0ull;
        #pragma unroll
        for (int q = 0; q < PD4; q++) {
            ulonglong2 v = sxu[j * PD4 + q];
            ulonglong2 w = seu[j * PD4 + q];
            ffma2(dxA2, xA[q].x, v.x);  ffma2(dxA2, xA[q].y, v.y);
            ffma2(deA2, eA[q].x, w.x);  ffma2(deA2, eA[q].y, w.y);
            ffma2(dxB2, xB[q].x, v.x);  ffma2(dxB2, xB[q].y, v.y);
            ffma2(deB2, eB[q].x, w.x);  ffma2(deB2, eB[q].y, w.y);
        }
        float dxA = lo32(dxA2) + hi32(dxA2);
        float deA = lo32(deA2) + hi32(deA2);
        float dxB = lo32(dxB2) + hi32(dxB2);
        float deB = lo32(deB2) + hi32(deB2);

        int jg = j0 + j;
        float denA = c1 * (sqA + ssq[j] - 2.0f * dxA) + p * deA;
        float denB = c1 * (sqB + ssq[j] - 2.0f * dxB) + p * deB;
        float aA = (jg == cgA) ? 1.0f : __fdividef((float)Dd, denA);
        float aB = (jg == cgB) ? 1.0f : __fdividef((float)Dd, denB);

        if (patient_tile) {
            // argmin-denominator key (== argmax sim, first-index tie-break)
            u64 kA = (((u64)__float_as_uint(denA)) << 32) | (unsigned)cA;
            u64 kB = (((u64)__float_as_uint(denB)) << 32) | (unsigned)cB;
            skey[cp][j] = (kA < kB) ? kA : kB;
        }

        u64 a2A = pack2(aA, aA);
        u64 a2B = pack2(aB, aB);
        #pragma unroll
        for (int h = 0; h < HIDh / 2; h++) {
            u64 gv = sg2[j * 17 + h];
            ffma2(accA[h], a2A, gv);
            ffma2(accB[h], a2B, gv);
        }
    }

    if (patient_tile) {
        __syncthreads();
        if (tid < JT) {
            u64 m = skey[0][tid];
            #pragma unroll
            for (int q = 1; q < 8; q++) {
                u64 v = skey[q][tid];
                if (v < m) m = v;
            }
            g_key[(size_t)(j0 + tid) * NIT + it] = m;   // [patient][tile]
        }
    }

    // unpack f32x2 accumulators, then distributed butterfly reduction:
    // lane s ends holding the lane-sum for h = s.
    float fA[HIDh], fB[HIDh];
    #pragma unroll
    for (int h = 0; h < HIDh / 2; h++) {
        fA[2 * h] = lo32(accA[h]);  fA[2 * h + 1] = hi32(accA[h]);
        fB[2 * h] = lo32(accB[h]);  fB[2 * h + 1] = hi32(accB[h]);
    }
    #pragma unroll
    for (int d = 16; d >= 1; d >>= 1) {
        #pragma unroll
        for (int i = 0; i < d; i++) {
            float sendA = (s & d) ? fA[i] : fA[i + d];
            float sendB = (s & d) ? fB[i] : fB[i + d];
            float recvA = __shfl_xor_sync(0xffffffffu, sendA, d);
            float recvB = __shfl_xor_sync(0xffffffffu, sendB, d);
            fA[i] = ((s & d) ? fA[i + d] : fA[i]) + recvA;
            fB[i] = ((s & d) ? fB[i + d] : fB[i]) + recvB;
        }
    }
    g_partial[((size_t)jt * NCc + cA) * HIDh + s] = fA[0];
    g_partial[((size_t)jt * NCc + cB) * HIDh + s] = fB[0];
}

// ============================================================
// K4: reduce partials (4 warps) -> sigmoid MLP -> group_embedding ->
//     gelu/imp chain -> scores.  grid = NCc, block = 128.
// ============================================================
__global__ void k4_emb(const float* __restrict__ gcn_b,
                       const float* __restrict__ out_w,
                       const float* __restrict__ out_b,
                       const float* __restrict__ w1,
                       const float* __restrict__ b1,
                       const float* __restrict__ w2,
                       const float* __restrict__ b2,
                       float* __restrict__ out) {
    __shared__ float sp[4 * HIDh];
    __shared__ float seh[HIDh];
    __shared__ float semb[Dd];
    __shared__ float shq[SQq];

    int c = blockIdx.x;
    int w = threadIdx.x >> 5;
    int h = threadIdx.x & 31;

    // warp w sums jt in [w*9, min(34, w*9+9)); ascending, deterministic.
    int jt0 = w * 9;
    int jt1 = (w == 3) ? NJT : jt0 + 9;
    float ps = 0.0f;
    const float* pp = &g_partial[(size_t)c * HIDh + h];
    #pragma unroll 9
    for (int jt = jt0; jt < jt1; jt++)
        ps += pp[(size_t)jt * (NCc * HIDh)];
    sp[w * HIDh + h] = ps;
    __syncthreads();

    if (w == 0) {
        float eh = gcn_b[h] + sp[h] + sp[HIDh + h] + sp[2 * HIDh + h] + sp[3 * HIDh + h];
        seh[h] = eh;
        __syncwarp();

        if (h < Dd) {
            float v = out_b[h];
            #pragma unroll
            for (int q = 0; q < HIDh; q++) v += seh[q] * out_w[q * Dd + h];
            v = 1.0f / (1.0f + expf(-v));
            semb[h] = v;
            g_ge[c * Dd + h] = v;
            out[OUT_GE + c * Dd + h] = v;
        }
        __syncwarp();

        if (h < SQq) {
            float v = b1[h];
            #pragma unroll
            for (int k = 0; k < Dd; k++) v += semb[k] * w1[k * SQq + h];
            shq[h] = 0.5f * v * (1.0f + erff(v * 0.70710678118654752f));
        }
        __syncwarp();

        if (h < Dd) {
            float v = b2[h];
            #pragma unroll
            for (int q = 0; q < SQq; q++) v += shq[q] * w2[q * Dd + h];
            g_sc[c * Dd + h] = 1.0f / (1.0f + expf(-v));
        }
    }
}

// ============================================================
// K5: reduce 16 per-tile keys per patient (one 128B line, ulonglong2
// vector loads) -> label; gather score/embedding rows.
// grid = 256, block = 128: 16 patients/block, 8 lanes/patient.
// ============================================================
__global__ void k5_gather(float* __restrict__ out) {
    int tid = threadIdx.x;
    int pl = tid >> 3, l8 = tid & 7;
    int jp = blockIdx.x * 16 + pl;

    ulonglong2 kv = ((const ulonglong2*)g_key)[(size_t)jp * 8 + l8];
    u64 best = (kv.x < kv.y) ? kv.x : kv.y;
    u64 o;
    o = __shfl_xor_sync(0xffffffffu, best, 1); if (o < best) best = o;
    o = __shfl_xor_sync(0xffffffffu, best, 2); if (o < best) best = o;
    o = __shfl_xor_sync(0xffffffffu, best, 4); if (o < best) best = o;
    int lane = tid & 31;
    best = __shfl_sync(0xffffffffu, best, lane & ~7);

    int label = (int)(unsigned)(best & 0xFFFFFFFFull);
    #pragma unroll
    for (int k = l8; k < Dd; k += 8) {
        out[OUT_GS + jp * Dd + k]  = g_sc[label * Dd + k];
        out[OUT_GPE + jp * Dd + k] = g_ge[label * Dd + k];
    }
    if (l8 == 0) out[OUT_GL + jp] = (float)label;
}

// ============================================================
extern "C" void kernel_launch(void* const* d_in, const int* in_sizes, int n_in,
                              void* d_out, int out_size) {
    const float* x        = (const float*)d_in[0];
    const float* dc       = (const float*)d_in[1];
    const float* centers  = (const float*)d_in[2];
    const float* proj_w   = (const float*)d_in[3];
    const float* proj_b   = (const float*)d_in[4];
    const float* dc_param = (const float*)d_in[5];
    const float* cc       = (const float*)d_in[6];
    const float* gcn_w    = (const float*)d_in[7];
    const float* gcn_b    = (const float*)d_in[8];
    const float* out_w    = (const float*)d_in[9];
    const float* out_b    = (const float*)d_in[10];
    const float* w1       = (const float*)d_in[11];
    const float* b1       = (const float*)d_in[12];
    const float* w2       = (const float*)d_in[13];
    const float* b2       = (const float*)d_in[14];
    float* out = (float*)d_out;

    k1_prep<<<Bp / 2 + 1, 256>>>(x, dc, gcn_w, centers, proj_w, proj_b, cc);
    k3_main<<<dim3(NJT, NIT), 256>>>(dc_param);
    k4_emb<<<NCc, 128>>>(gcn_b, out_w, out_b, w1, b1, w2, b2, out);
    k5_gather<<<256, 128>>>(out);
}

// round 6
// speedup vs baseline: 2.7153x; 1.0082x over previous
#include <cuda_runtime.h>
#include <cstdint>
#include <math.h>

// Problem constants
#define Bp   4096
#define Dd   19
#define Ff   64
#define NCc  256
#define HIDh 32
#define SQq  16
#define Nn   (Bp + NCc)
#define PD   20            // padded row stride (19 + 1 zero pad), float4-able
#define PD4  5             // PD/4

// K3 tiling
#define JT   128            // j per tile
#define NJT  (Nn / JT)      // 34
#define NPJT (Bp / JT)      // 32 patient-only tiles
#define IT   16             // centers per block (8 thread-pairs x 2)
#define NIT  (NCc / IT)     // 16

// Output offsets (floats)
#define OUT_GS  0
#define OUT_GE  (Bp * Dd)
#define OUT_GPE ((Bp + NCc) * Dd)
#define OUT_GL  (((2 * Bp) + NCc) * Dd)

typedef unsigned long long u64;

// -------- device scratch (no allocations allowed) --------
__device__ float4 g_x4[Nn * PD4];          // x_all rows, padded, pad = 0
__device__ float4 g_e4[Nn * PD4];          // e rows, padded, pad = 0
__device__ float  g_sq[Nn];
__device__ float4 g_g4[Nn * (HIDh / 4)];   // g = x_all @ gcn_w
__device__ float  g_partial[NJT * NCc * HIDh];
__device__ u64    g_key[Bp * NIT];         // [patient][center-tile] argmin key
__device__ float  g_ge[NCc * Dd];
__device__ float  g_sc[NCc * Dd];

// PDL: wait until the upstream (stream-predecessor) grid's memory is visible.
__device__ __forceinline__ void gdc_wait() {
    asm volatile("griddepcontrol.wait;" ::: "memory");
}
// PDL: allow dependents to launch (also implicit at kernel completion).
__device__ __forceinline__ void gdc_launch_dependents() {
    asm volatile("griddepcontrol.launch_dependents;" ::: "memory");
}

// packed f32x2 fma: d = a*b + d (FFMA2, PTX-only on sm_103a)
__device__ __forceinline__ void ffma2(u64& d, u64 a, u64 b) {
    asm("fma.rn.f32x2 %0, %1, %2, %0;" : "+l"(d) : "l"(a), "l"(b));
}
__device__ __forceinline__ float lo32(u64 v) {
    return __uint_as_float((unsigned)(v & 0xFFFFFFFFull));
}
__device__ __forceinline__ float hi32(u64 v) {
    return __uint_as_float((unsigned)(v >> 32));
}
__device__ __forceinline__ u64 pack2(float a, float b) {
    u64 r;
    asm("mov.b64 %0, {%1, %2};" : "=l"(r) : "r"(__float_as_uint(a)), "r"(__float_as_uint(b)));
    return r;
}

// ============================================================
// K1: blocks 0..2047: two patients each (x_avg, e, sq, g).
//     block 2048: all 256 centers (proj + e + sq + g).
// block = 256
// ============================================================
__global__ void k1_prep(const float* __restrict__ x,
                        const float* __restrict__ dc,
                        const float* __restrict__ gcn_w,
                        const float* __restrict__ centers,
                        const float* __restrict__ proj_w,
                        const float* __restrict__ proj_b,
                        const float* __restrict__ cc) {
    __shared__ float sxa[2][PD];
    __shared__ float sw[Dd * HIDh];
    __shared__ float spw[61 * Dd];
    __shared__ float spb[Dd];
    int tid = threadIdx.x;
    float* gx = (float*)g_x4;
    float* ge = (float*)g_e4;
    float* gg = (float*)g_g4;

    if (blockIdx.x < Bp / 2) {
        // ---- patients ----
        for (int i = tid; i < Dd * HIDh; i += 256) sw[i] = gcn_w[i];

        int ps   = tid >> 7;                 // patient slot 0/1
        int t128 = tid & 127;
        int wp   = (t128 >> 5);              // warp-in-patient 0..3
        int lane = tid & 31;
        int b = blockIdx.x * 2 + ps;

        const float* xb = x + (size_t)b * (Dd * Ff);
        for (int d = wp; d < Dd; d += 4) {
            float v = xb[d * Ff + lane] + xb[d * Ff + lane + 32];
            v += __shfl_down_sync(0xffffffffu, v, 16);
            v += __shfl_down_sync(0xffffffffu, v, 8);
            v += __shfl_down_sync(0xffffffffu, v, 4);
            v += __shfl_down_sync(0xffffffffu, v, 2);
            v += __shfl_down_sync(0xffffffffu, v, 1);
            if (lane == 0) sxa[ps][d] = v * (1.0f / 64.0f);
        }
        __syncthreads();

        if (t128 < PD) {
            int k = t128;
            float xa = (k < Dd) ? sxa[ps][k] : 0.0f;
            gx[b * PD + k] = xa;
            ge[b * PD + k] = (k < Dd) ? expf(1.0f - dc[b * Dd + k]) : 0.0f;
        }
        if (t128 == 32) {
            float s = 0.0f;
            #pragma unroll
            for (int k = 0; k < Dd; k++) s += sxa[ps][k] * sxa[ps][k];
            g_sq[b] = s;
        }
        if (t128 >= 64 && t128 < 64 + HIDh) {
            int h = t128 - 64;
            float acc = 0.0f;
            #pragma unroll
            for (int k = 0; k < Dd; k++) acc += sxa[ps][k] * sw[k * HIDh + h];
            gg[b * HIDh + h] = acc;
        }
    } else {
        // ---- centers (one block, thread c = center) ----
        for (int i = tid; i < 61 * Dd; i += 256) spw[i] = proj_w[i];
        if (tid < Dd) spb[tid] = proj_b[tid];
        for (int i = tid; i < Dd * HIDh; i += 256) sw[i] = gcn_w[i];
        __syncthreads();

        int c = tid;
        float cp[Dd];
        #pragma unroll
        for (int k = 0; k < Dd; k++) cp[k] = spb[k];
        for (int m = 0; m < 61; m++) {
            float cm = centers[c * 61 + m];
            #pragma unroll
            for (int k = 0; k < Dd; k++) cp[k] += cm * spw[m * Dd + k];
        }
        int row = Bp + c;
        float s = 0.0f;
        #pragma unroll
        for (int k = 0; k < Dd; k++) {
            gx[row * PD + k] = cp[k];
            s += cp[k] * cp[k];
            ge[row * PD + k] = expf(1.0f - cc[c * Dd + k]);
        }
        gx[row * PD + Dd] = 0.0f;
        ge[row * PD + Dd] = 0.0f;
        g_sq[row] = s;
        #pragma unroll
        for (int h = 0; h < HIDh; h++) {
            float acc = 0.0f;
            #pragma unroll
            for (int k = 0; k < Dd; k++) acc += cp[k] * sw[k * HIDh + h];
            gg[row * HIDh + h] = acc;
        }
    }
}

// ============================================================
// K3: fused adjacency + adj@g for center rows (CB=2, f32x2 packed math)
//     + per-(patient, center-tile) argmin key emission.
// grid = (NJT, NIT), block = 256: thread = (cp 0..7, s 0..31).
// ============================================================
__global__ void __launch_bounds__(256) k3_main(const float* __restrict__ p_ptr) {
    __shared__ ulonglong2 sxu[JT * PD4];      // x rows, 16B granules (f32x2 pairs)
    __shared__ ulonglong2 seu[JT * PD4];
    __shared__ u64  sg2[JT * 17];             // g rows: 16 u64 + 1 pad (stride 17)
    __shared__ float ssq[JT];
    __shared__ u64 skey[8][JT + 1];           // [cp][j], +1 pad

    int tid = threadIdx.x;
    int jt = blockIdx.x, it = blockIdx.y;
    int j0 = jt * JT;
    bool patient_tile = (jt < NPJT);

    float p = *p_ptr;        // input-only, safe pre-wait
    float c1 = 1.0f - p;

    gdc_wait();              // k1's writes must be visible

    const ulonglong2* gx = (const ulonglong2*)g_x4;
    const ulonglong2* geu = (const ulonglong2*)g_e4;
    for (int i = tid; i < JT * PD4; i += 256) {
        sxu[i] = gx[j0 * PD4 + i];
        seu[i] = geu[j0 * PD4 + i];
    }
    for (int i = tid; i < JT * (HIDh / 4); i += 256) {
        int j = i >> 3, q = i & 7;
        float4 gv = g_g4[(size_t)(j0 + j) * (HIDh / 4) + q];
        sg2[j * 17 + q * 2 + 0] = pack2(gv.x, gv.y);
        sg2[j * 17 + q * 2 + 1] = pack2(gv.z, gv.w);
    }
    if (tid < JT) ssq[tid] = g_sq[j0 + tid];

    int cp = tid >> 5, s = tid & 31;
    int cA = it * IT + cp * 2;
    int cB = cA + 1;
    int cgA = Bp + cA, cgB = Bp + cB;

    ulonglong2 xA[PD4], eA[PD4], xB[PD4], eB[PD4];
    #pragma unroll
    for (int q = 0; q < PD4; q++) {
        xA[q] = gx[cgA * PD4 + q];
        eA[q] = geu[cgA * PD4 + q];
        xB[q] = gx[cgB * PD4 + q];
        eB[q] = geu[cgB * PD4 + q];
    }
    float sqA = g_sq[cgA], sqB = g_sq[cgB];
    __syncthreads();

    u64 accA[HIDh / 2], accB[HIDh / 2];
    #pragma unroll
    for (int h = 0; h < HIDh / 2; h++) { accA[h] = 0ull; accB[h] = 0ull; }

    #pragma unroll
    for (int t = 0; t < JT / 32; t++) {
        int j = s + 32 * t;
        u64 dxA2 = 0ull, deA2 = 0ull, dxB2 = 0ull, deB2 = 0ull;
        #pragma unroll
        for (int q = 0; q < PD4; q++) {
            ulonglong2 v = sxu[j * PD4 + q];
            ulonglong2 w = seu[j * PD4 + q];
            ffma2(dxA2, xA[q].x, v.x);  ffma2(dxA2, xA[q].y, v.y);
            ffma2(deA2, eA[q].x, w.x);  ffma2(deA2, eA[q].y, w.y);
            ffma2(dxB2, xB[q].x, v.x);  ffma2(dxB2, xB[q].y, v.y);
            ffma2(deB2, eB[q].x, w.x);  ffma2(deB2, eB[q].y, w.y);
        }
        float dxA = lo32(dxA2) + hi32(dxA2);
        float deA = lo32(deA2) + hi32(deA2);
        float dxB = lo32(dxB2) + hi32(dxB2);
        float deB = lo32(deB2) + hi32(deB2);

        int jg = j0 + j;
        float denA = c1 * (sqA + ssq[j] - 2.0f * dxA) + p * deA;
        float denB = c1 * (sqB + ssq[j] - 2.0f * dxB) + p * deB;
        float aA = (jg == cgA) ? 1.0f : __fdividef((float)Dd, denA);
        float aB = (jg == cgB) ? 1.0f : __fdividef((float)Dd, denB);

        if (patient_tile) {
            // argmin-denominator key (== argmax sim, first-index tie-break)
            u64 kA = (((u64)__float_as_uint(denA)) << 32) | (unsigned)cA;
            u64 kB = (((u64)__float_as_uint(denB)) << 32) | (unsigned)cB;
            skey[cp][j] = (kA < kB) ? kA : kB;
        }

        u64 a2A = pack2(aA, aA);
        u64 a2B = pack2(aB, aB);
        #pragma unroll
        for (int h = 0; h < HIDh / 2; h++) {
            u64 gv = sg2[j * 17 + h];
            ffma2(accA[h], a2A, gv);
            ffma2(accB[h], a2B, gv);
        }
    }

    if (patient_tile) {
        __syncthreads();
        if (tid < JT) {
            u64 m = skey[0][tid];
            #pragma unroll
            for (int q = 1; q < 8; q++) {
                u64 v = skey[q][tid];
                if (v < m) m = v;
            }
            g_key[(size_t)(j0 + tid) * NIT + it] = m;   // [patient][tile]
        }
    }

    // unpack f32x2 accumulators, then distributed butterfly reduction:
    // lane s ends holding the lane-sum for h = s.
    float fA[HIDh], fB[HIDh];
    #pragma unroll
    for (int h = 0; h < HIDh / 2; h++) {
        fA[2 * h] = lo32(accA[h]);  fA[2 * h + 1] = hi32(accA[h]);
        fB[2 * h] = lo32(accB[h]);  fB[2 * h + 1] = hi32(accB[h]);
    }
    #pragma unroll
    for (int d = 16; d >= 1; d >>= 1) {
        #pragma unroll
        for (int i = 0; i < d; i++) {
            float sendA = (s & d) ? fA[i] : fA[i + d];
            float sendB = (s & d) ? fB[i] : fB[i + d];
            float recvA = __shfl_xor_sync(0xffffffffu, sendA, d);
            float recvB = __shfl_xor_sync(0xffffffffu, sendB, d);
            fA[i] = ((s & d) ? fA[i + d] : fA[i]) + recvA;
            fB[i] = ((s & d) ? fB[i + d] : fB[i]) + recvB;
        }
    }
    g_partial[((size_t)jt * NCc + cA) * HIDh + s] = fA[0];
    g_partial[((size_t)jt * NCc + cB) * HIDh + s] = fB[0];
}

// ============================================================
// K4: reduce partials (4 warps) -> sigmoid MLP -> group_embedding ->
//     gelu/imp chain -> scores.  grid = NCc, block = 128.
// ============================================================
__global__ void k4_emb(const float* __restrict__ gcn_b,
                       const float* __restrict__ out_w,
                       const float* __restrict__ out_b,
                       const float* __restrict__ w1,
                       const float* __restrict__ b1,
                       const float* __restrict__ w2,
                       const float* __restrict__ b2,
                       float* __restrict__ out) {
    __shared__ float sp[4 * HIDh];
    __shared__ float seh[HIDh];
    __shared__ float semb[Dd];
    __shared__ float shq[SQq];

    int c = blockIdx.x;
    int w = threadIdx.x >> 5;
    int h = threadIdx.x & 31;

    float bias = gcn_b[h];   // input-only, safe pre-wait
    gdc_wait();              // k3's partials must be visible

    // warp w sums jt in [w*9, min(34, w*9+9)); ascending, deterministic.
    int jt0 = w * 9;
    int jt1 = (w == 3) ? NJT : jt0 + 9;
    float ps = 0.0f;
    const float* pp = &g_partial[(size_t)c * HIDh + h];
    #pragma unroll 9
    for (int jt = jt0; jt < jt1; jt++)
        ps += pp[(size_t)jt * (NCc * HIDh)];
    sp[w * HIDh + h] = ps;
    __syncthreads();

    if (w == 0) {
        float eh = bias + sp[h] + sp[HIDh + h] + sp[2 * HIDh + h] + sp[3 * HIDh + h];
        seh[h] = eh;
        __syncwarp();

        if (h < Dd) {
            float v = out_b[h];
            #pragma unroll
            for (int q = 0; q < HIDh; q++) v += seh[q] * out_w[q * Dd + h];
            v = 1.0f / (1.0f + expf(-v));
            semb[h] = v;
            g_ge[c * Dd + h] = v;
            out[OUT_GE + c * Dd + h] = v;
        }
        __syncwarp();

        if (h < SQq) {
            float v = b1[h];
            #pragma unroll
            for (int k = 0; k < Dd; k++) v += semb[k] * w1[k * SQq + h];
            shq[h] = 0.5f * v * (1.0f + erff(v * 0.70710678118654752f));
        }
        __syncwarp();

        if (h < Dd) {
            float v = b2[h];
            #pragma unroll
            for (int q = 0; q < SQq; q++) v += shq[q] * w2[q * Dd + h];
            g_sc[c * Dd + h] = 1.0f / (1.0f + expf(-v));
        }
    }
}

// ============================================================
// K5: reduce 16 per-tile keys per patient (one 128B line) -> label;
// then PDL-wait on k4 and gather score/embedding rows.
// The key reduction reads g_key (produced by k3, which completed before
// k4 started), so it runs CONCURRENTLY with k4 under PDL; only the
// gather sits behind the wait.
// grid = 256, block = 128: 16 patients/block, 8 lanes/patient.
// ============================================================
__global__ void k5_gather(float* __restrict__ out) {
    int tid = threadIdx.x;
    int pl = tid >> 3, l8 = tid & 7;
    int jp = blockIdx.x * 16 + pl;

    ulonglong2 kv = ((const ulonglong2*)g_key)[(size_t)jp * 8 + l8];
    u64 best = (kv.x < kv.y) ? kv.x : kv.y;
    u64 o;
    o = __shfl_xor_sync(0xffffffffu, best, 1); if (o < best) best = o;
    o = __shfl_xor_sync(0xffffffffu, best, 2); if (o < best) best = o;
    o = __shfl_xor_sync(0xffffffffu, best, 4); if (o < best) best = o;
    int lane = tid & 31;
    best = __shfl_sync(0xffffffffu, best, lane & ~7);

    int label = (int)(unsigned)(best & 0xFFFFFFFFull);

    gdc_wait();              // k4's g_sc / g_ge must be visible

    #pragma unroll
    for (int k = l8; k < Dd; k += 8) {
        out[OUT_GS + jp * Dd + k]  = g_sc[label * Dd + k];
        out[OUT_GPE + jp * Dd + k] = g_ge[label * Dd + k];
    }
    if (l8 == 0) out[OUT_GL + jp] = (float)label;
}

// ============================================================
template <typename... Args>
static inline void launch_pdl(void (*kern)(Args...), dim3 grid, dim3 block,
                              Args... args) {
    cudaLaunchConfig_t cfg = {};
    cfg.gridDim = grid;
    cfg.blockDim = block;
    cfg.dynamicSmemBytes = 0;
    cfg.stream = 0;
    cudaLaunchAttribute attr[1];
    attr[0].id = cudaLaunchAttributeProgrammaticStreamSerialization;
    attr[0].val.programmaticStreamSerializationAllowed = 1;
    cfg.attrs = attr;
    cfg.numAttrs = 1;
    cudaLaunchKernelEx(&cfg, kern, args...);
}

extern "C" void kernel_launch(void* const* d_in, const int* in_sizes, int n_in,
                              void* d_out, int out_size) {
    const float* x        = (const float*)d_in[0];
    const float* dc       = (const float*)d_in[1];
    const float* centers  = (const float*)d_in[2];
    const float* proj_w   = (const float*)d_in[3];
    const float* proj_b   = (const float*)d_in[4];
    const float* dc_param = (const float*)d_in[5];
    const float* cc       = (const float*)d_in[6];
    const float* gcn_w    = (const float*)d_in[7];
    const float* gcn_b    = (const float*)d_in[8];
    const float* out_w    = (const float*)d_in[9];
    const float* out_b    = (const float*)d_in[10];
    const float* w1       = (const float*)d_in[11];
    const float* b1       = (const float*)d_in[12];
    const float* w2       = (const float*)d_in[13];
    const float* b2       = (const float*)d_in[14];
    float* out = (float*)d_out;

    k1_prep<<<Bp / 2 + 1, 256>>>(x, dc, gcn_w, centers, proj_w, proj_b, cc);
    launch_pdl(k3_main, dim3(NJT, NIT), dim3(256), dc_param);
    launch_pdl(k4_emb, dim3(NCc), dim3(128),
               gcn_b, out_w, out_b, w1, b1, w2, b2, out);
    launch_pdl(k5_gather, dim3(256), dim3(128), out);
}

// round 7
// speedup vs baseline: 2.7194x; 1.0015x over previous
#include <cuda_runtime.h>
#include <cstdint>
#include <math.h>

// Problem constants
#define Bp   4096
#define Dd   19
#define Ff   64
#define NCc  256
#define HIDh 32
#define SQq  16
#define Nn   (Bp + NCc)
#define PD   20            // padded row stride (19 + 1 zero pad), float4-able
#define PD4  5             // PD/4

// K3 tiling
#define JT   128            // j per tile
#define NJT  (Nn / JT)      // 34
#define NPJT (Bp / JT)      // 32 patient-only tiles
#define IT   16             // centers per block (8 thread-pairs x 2)
#define NIT  (NCc / IT)     // 16

// Output offsets (floats)
#define OUT_GS  0
#define OUT_GE  (Bp * Dd)
#define OUT_GPE ((Bp + NCc) * Dd)
#define OUT_GL  (((2 * Bp) + NCc) * Dd)

typedef unsigned long long u64;

// -------- device scratch (no allocations allowed) --------
__device__ float4 g_x4[Nn * PD4];          // x_all rows, padded, pad = 0
__device__ float4 g_e4[Nn * PD4];          // e rows, padded, pad = 0
__device__ float  g_sq[Nn];
__device__ float4 g_g4[Nn * (HIDh / 4)];   // g = x_all @ gcn_w
__device__ float  g_partial[NJT * NCc * HIDh];
__device__ u64    g_key[Bp * NIT];         // [patient][center-tile] argmin key
__device__ float  g_ge[NCc * Dd];
__device__ float  g_sc[NCc * Dd];

// PDL: wait until the upstream (stream-predecessor) grid's memory is visible.
__device__ __forceinline__ void gdc_wait() {
    asm volatile("griddepcontrol.wait;" ::: "memory");
}
// PDL: allow dependents to launch (also implicit at kernel completion).
__device__ __forceinline__ void gdc_launch_dependents() {
    asm volatile("griddepcontrol.launch_dependents;" ::: "memory");
}

// packed f32x2 fma: d = a*b + d (FFMA2, PTX-only on sm_103a)
__device__ __forceinline__ void ffma2(u64& d, u64 a, u64 b) {
    asm("fma.rn.f32x2 %0, %1, %2, %0;" : "+l"(d) : "l"(a), "l"(b));
}
__device__ __forceinline__ float lo32(u64 v) {
    return __uint_as_float((unsigned)(v & 0xFFFFFFFFull));
}
__device__ __forceinline__ float hi32(u64 v) {
    return __uint_as_float((unsigned)(v >> 32));
}
__device__ __forceinline__ u64 pack2(float a, float b) {
    u64 r;
    asm("mov.b64 %0, {%1, %2};" : "=l"(r) : "r"(__float_as_uint(a)), "r"(__float_as_uint(b)));
    return r;
}

// ============================================================
// K1: blocks 0..2047: two patients each (x_avg, e, sq, g).
//     block 2048: all 256 centers (proj + e + sq + g).
// block = 256
// ============================================================
__global__ void k1_prep(const float* __restrict__ x,
                        const float* __restrict__ dc,
                        const float* __restrict__ gcn_w,
                        const float* __restrict__ centers,
                        const float* __restrict__ proj_w,
                        const float* __restrict__ proj_b,
                        const float* __restrict__ cc) {
    __shared__ float sxa[2][PD];
    __shared__ float sw[Dd * HIDh];
    __shared__ float spw[61 * Dd];
    __shared__ float spb[Dd];
    int tid = threadIdx.x;
    float* gx = (float*)g_x4;
    float* ge = (float*)g_e4;
    float* gg = (float*)g_g4;

    if (blockIdx.x < Bp / 2) {
        // ---- patients ----
        for (int i = tid; i < Dd * HIDh; i += 256) sw[i] = gcn_w[i];

        int ps   = tid >> 7;                 // patient slot 0/1
        int t128 = tid & 127;
        int wp   = (t128 >> 5);              // warp-in-patient 0..3
        int lane = tid & 31;
        int b = blockIdx.x * 2 + ps;

        const float* xb = x + (size_t)b * (Dd * Ff);
        for (int d = wp; d < Dd; d += 4) {
            float v = xb[d * Ff + lane] + xb[d * Ff + lane + 32];
            v += __shfl_down_sync(0xffffffffu, v, 16);
            v += __shfl_down_sync(0xffffffffu, v, 8);
            v += __shfl_down_sync(0xffffffffu, v, 4);
            v += __shfl_down_sync(0xffffffffu, v, 2);
            v += __shfl_down_sync(0xffffffffu, v, 1);
            if (lane == 0) sxa[ps][d] = v * (1.0f / 64.0f);
        }
        __syncthreads();

        if (t128 < PD) {
            int k = t128;
            float xa = (k < Dd) ? sxa[ps][k] : 0.0f;
            gx[b * PD + k] = xa;
            ge[b * PD + k] = (k < Dd) ? expf(1.0f - dc[b * Dd + k]) : 0.0f;
        }
        if (t128 == 32) {
            float s = 0.0f;
            #pragma unroll
            for (int k = 0; k < Dd; k++) s += sxa[ps][k] * sxa[ps][k];
            g_sq[b] = s;
        }
        if (t128 >= 64 && t128 < 64 + HIDh) {
            int h = t128 - 64;
            float acc = 0.0f;
            #pragma unroll
            for (int k = 0; k < Dd; k++) acc += sxa[ps][k] * sw[k * HIDh + h];
            gg[b * HIDh + h] = acc;
        }
    } else {
        // ---- centers (one block, thread c = center) ----
        for (int i = tid; i < 61 * Dd; i += 256) spw[i] = proj_w[i];
        if (tid < Dd) spb[tid] = proj_b[tid];
        for (int i = tid; i < Dd * HIDh; i += 256) sw[i] = gcn_w[i];
        __syncthreads();

        int c = tid;
        float cp[Dd];
        #pragma unroll
        for (int k = 0; k < Dd; k++) cp[k] = spb[k];
        for (int m = 0; m < 61; m++) {
            float cm = centers[c * 61 + m];
            #pragma unroll
            for (int k = 0; k < Dd; k++) cp[k] += cm * spw[m * Dd + k];
        }
        int row = Bp + c;
        float s = 0.0f;
        #pragma unroll
        for (int k = 0; k < Dd; k++) {
            gx[row * PD + k] = cp[k];
            s += cp[k] * cp[k];
            ge[row * PD + k] = expf(1.0f - cc[c * Dd + k]);
        }
        gx[row * PD + Dd] = 0.0f;
        ge[row * PD + Dd] = 0.0f;
        g_sq[row] = s;
        #pragma unroll
        for (int h = 0; h < HIDh; h++) {
            float acc = 0.0f;
            #pragma unroll
            for (int k = 0; k < Dd; k++) acc += cp[k] * sw[k * HIDh + h];
            gg[row * HIDh + h] = acc;
        }
    }
}

// ============================================================
// K3: fused adjacency + adj@g for center rows (CB=2, f32x2 packed math)
//     + per-(patient, center-tile) argmin key emission.
// grid = (NJT, NIT), block = 256: thread = (cp 0..7, s 0..31).
// ============================================================
__global__ void __launch_bounds__(256) k3_main(const float* __restrict__ p_ptr) {
    __shared__ ulonglong2 sxu[JT * PD4];      // x rows, 16B granules (f32x2 pairs)
    __shared__ ulonglong2 seu[JT * PD4];
    __shared__ u64  sg2[JT * 17];             // g rows: 16 u64 + 1 pad (stride 17)
    __shared__ float ssq[JT];
    __shared__ u64 skey[8][JT + 1];           // [cp][j], +1 pad

    int tid = threadIdx.x;
    int jt = blockIdx.x, it = blockIdx.y;
    int j0 = jt * JT;
    bool patient_tile = (jt < NPJT);

    float p = *p_ptr;        // input-only, safe pre-wait
    float c1 = 1.0f - p;

    gdc_wait();              // k1's writes must be visible

    const ulonglong2* gx = (const ulonglong2*)g_x4;
    const ulonglong2* geu = (const ulonglong2*)g_e4;
    for (int i = tid; i < JT * PD4; i += 256) {
        sxu[i] = gx[j0 * PD4 + i];
        seu[i] = geu[j0 * PD4 + i];
    }
    for (int i = tid; i < JT * (HIDh / 4); i += 256) {
        int j = i >> 3, q = i & 7;
        float4 gv = g_g4[(size_t)(j0 + j) * (HIDh / 4) + q];
        sg2[j * 17 + q * 2 + 0] = pack2(gv.x, gv.y);
        sg2[j * 17 + q * 2 + 1] = pack2(gv.z, gv.w);
    }
    if (tid < JT) ssq[tid] = g_sq[j0 + tid];

    int cp = tid >> 5, s = tid & 31;
    int cA = it * IT + cp * 2;
    int cB = cA + 1;
    int cgA = Bp + cA, cgB = Bp + cB;

    ulonglong2 xA[PD4], eA[PD4], xB[PD4], eB[PD4];
    #pragma unroll
    for (int q = 0; q < PD4; q++) {
        xA[q] = gx[cgA * PD4 + q];
        eA[q] = geu[cgA * PD4 + q];
        xB[q] = gx[cgB * PD4 + q];
        eB[q] = geu[cgB * PD4 + q];
    }
    float sqA = g_sq[cgA], sqB = g_sq[cgB];
    __syncthreads();

    u64 accA[HIDh / 2], accB[HIDh / 2];
    #pragma unroll
    for (int h = 0; h < HIDh / 2; h++) { accA[h] = 0ull; accB[h] = 0ull; }

    #pragma unroll
    for (int t = 0; t < JT / 32; t++) {
        int j = s + 32 * t;
        u64 dxA2 = 0ull, deA2 = 0ull, dxB2 = 0ull, deB2 = 0ull;
        #pragma unroll
        for (int q = 0; q < PD4; q++) {
            ulonglong2 v = sxu[j * PD4 + q];
            ulonglong2 w = seu[j * PD4 + q];
            ffma2(dxA2, xA[q].x, v.x);  ffma2(dxA2, xA[q].y, v.y);
            ffma2(deA2, eA[q].x, w.x);  ffma2(deA2, eA[q].y, w.y);
            ffma2(dxB2, xB[q].x, v.x);  ffma2(dxB2, xB[q].y, v.y);
            ffma2(deB2, eB[q].x, w.x);  ffma2(deB2, eB[q].y, w.y);
        }
        float dxA = lo32(dxA2) + hi32(dxA2);
        float deA = lo32(deA2) + hi32(deA2);
        float dxB = lo32(dxB2) + hi32(dxB2);
        float deB = lo32(deB2) + hi32(deB2);

        int jg = j0 + j;
        float denA = c1 * (sqA + ssq[j] - 2.0f * dxA) + p * deA;
        float denB = c1 * (sqB + ssq[j] - 2.0f * dxB) + p * deB;
        float aA = (jg == cgA) ? 1.0f : __fdividef((float)Dd, denA);
        float aB = (jg == cgB) ? 1.0f : __fdividef((float)Dd, denB);

        if (patient_tile) {
            // argmin-denominator key (== argmax sim, first-index tie-break)
            u64 kA = (((u64)__float_as_uint(denA)) << 32) | (unsigned)cA;
            u64 kB = (((u64)__float_as_uint(denB)) << 32) | (unsigned)cB;
            skey[cp][j] = (kA < kB) ? kA : kB;
        }

        u64 a2A = pack2(aA, aA);
        u64 a2B = pack2(aB, aB);
        #pragma unroll
        for (int h = 0; h < HIDh / 2; h++) {
            u64 gv = sg2[j * 17 + h];
            ffma2(accA[h], a2A, gv);
            ffma2(accB[h], a2B, gv);
        }
    }

    if (patient_tile) {
        __syncthreads();
        if (tid < JT) {
            u64 m = skey[0][tid];
            #pragma unroll
            for (int q = 1; q < 8; q++) {
                u64 v = skey[q][tid];
                if (v < m) m = v;
            }
            g_key[(size_t)(j0 + tid) * NIT + it] = m;   // [patient][tile]
        }
    }

    // unpack f32x2 accumulators, then distributed butterfly reduction:
    // lane s ends holding the lane-sum for h = s.
    float fA[HIDh], fB[HIDh];
    #pragma unroll
    for (int h = 0; h < HIDh / 2; h++) {
        fA[2 * h] = lo32(accA[h]);  fA[2 * h + 1] = hi32(accA[h]);
        fB[2 * h] = lo32(accB[h]);  fB[2 * h + 1] = hi32(accB[h]);
    }
    #pragma unroll
    for (int d = 16; d >= 1; d >>= 1) {
        #pragma unroll
        for (int i = 0; i < d; i++) {
            float sendA = (s & d) ? fA[i] : fA[i + d];
            float sendB = (s & d) ? fB[i] : fB[i + d];
            float recvA = __shfl_xor_sync(0xffffffffu, sendA, d);
            float recvB = __shfl_xor_sync(0xffffffffu, sendB, d);
            fA[i] = ((s & d) ? fA[i + d] : fA[i]) + recvA;
            fB[i] = ((s & d) ? fB[i + d] : fB[i]) + recvB;
        }
    }
    g_partial[((size_t)jt * NCc + cA) * HIDh + s] = fA[0];
    g_partial[((size_t)jt * NCc + cB) * HIDh + s] = fB[0];
}

// ============================================================
// K4: reduce partials (4 warps) -> sigmoid MLP -> group_embedding ->
//     gelu/imp chain -> scores.  grid = NCc, block = 128.
// ============================================================
__global__ void k4_emb(const float* __restrict__ gcn_b,
                       const float* __restrict__ out_w,
                       const float* __restrict__ out_b,
                       const float* __restrict__ w1,
                       const float* __restrict__ b1,
                       const float* __restrict__ w2,
                       const float* __restrict__ b2,
                       float* __restrict__ out) {
    __shared__ float sp[4 * HIDh];
    __shared__ float seh[HIDh];
    __shared__ float semb[Dd];
    __shared__ float shq[SQq];

    int c = blockIdx.x;
    int w = threadIdx.x >> 5;
    int h = threadIdx.x & 31;

    float bias = gcn_b[h];   // input-only, safe pre-wait
    gdc_wait();              // k3's partials must be visible

    // warp w sums jt in [w*9, min(34, w*9+9)); ascending, deterministic.
    int jt0 = w * 9;
    int jt1 = (w == 3) ? NJT : jt0 + 9;
    float ps = 0.0f;
    const float* pp = &g_partial[(size_t)c * HIDh + h];
    #pragma unroll 9
    for (int jt = jt0; jt < jt1; jt++)
        ps += pp[(size_t)jt * (NCc * HIDh)];
    sp[w * HIDh + h] = ps;
    __syncthreads();

    if (w == 0) {
        float eh = bias + sp[h] + sp[HIDh + h] + sp[2 * HIDh + h] + sp[3 * HIDh + h];
        seh[h] = eh;
        __syncwarp();

        if (h < Dd) {
            float v = out_b[h];
            #pragma unroll
            for (int q = 0; q < HIDh; q++) v += seh[q] * out_w[q * Dd + h];
            v = 1.0f / (1.0f + expf(-v));
            semb[h] = v;
            g_ge[c * Dd + h] = v;
            out[OUT_GE + c * Dd + h] = v;
        }
        __syncwarp();

        if (h < SQq) {
            float v = b1[h];
            #pragma unroll
            for (int k = 0; k < Dd; k++) v += semb[k] * w1[k * SQq + h];
            shq[h] = 0.5f * v * (1.0f + erff(v * 0.70710678118654752f));
        }
        __syncwarp();

        if (h < Dd) {
            float v = b2[h];
            #pragma unroll
            for (int q = 0; q < SQq; q++) v += shq[q] * w2[q * Dd + h];
            g_sc[c * Dd + h] = 1.0f / (1.0f + expf(-v));
        }
    }
}

// ============================================================
// K5: reduce 16 per-tile keys per patient (one 128B line) -> label;
// then PDL-wait on k4 and gather score/embedding rows.
// The key reduction reads g_key (produced by k3, which completed before
// k4 started), so it runs CONCURRENTLY with k4 under PDL; only the
// gather sits behind the wait.
// grid = 256, block = 128: 16 patients/block, 8 lanes/patient.
// ============================================================
__global__ void k5_gather(float* __restrict__ out) {
    int tid = threadIdx.x;
    int pl = tid >> 3, l8 = tid & 7;
    int jp = blockIdx.x * 16 + pl;

    ulonglong2 kv = ((const ulonglong2*)g_key)[(size_t)jp * 8 + l8];
    u64 best = (kv.x < kv.y) ? kv.x : kv.y;
    u64 o;
    o = __shfl_xor_sync(0xffffffffu, best, 1); if (o < best) best = o;
    o = __shfl_xor_sync(0xffffffffu, best, 2); if (o < best) best = o;
    o = __shfl_xor_sync(0xffffffffu, best, 4); if (o < best) best = o;
    int lane = tid & 31;
    best = __shfl_sync(0xffffffffu, best, lane & ~7);

    int label = (int)(unsigned)(best & 0xFFFFFFFFull);

    gdc_wait();              // k4's g_sc / g_ge must be visible

    #pragma unroll
    for (int k = l8; k < Dd; k += 8) {
        out[OUT_GS + jp * Dd + k]  = g_sc[label * Dd + k];
        out[OUT_GPE + jp * Dd + k] = g_ge[label * Dd + k];
    }
    if (l8 == 0) out[OUT_GL + jp] = (float)label;
}

// ============================================================
template <typename... Args>
static inline void launch_pdl(void (*kern)(Args...), dim3 grid, dim3 block,
                              Args... args) {
    cudaLaunchConfig_t cfg = {};
    cfg.gridDim = grid;
    cfg.blockDim = block;
    cfg.dynamicSmemBytes = 0;
    cfg.stream = 0;
    cudaLaunchAttribute attr[1];
    attr[0].id = cudaLaunchAttributeProgrammaticStreamSerialization;
    attr[0].val.programmaticStreamSerializationAllowed = 1;
    cfg.attrs = attr;
    cfg.numAttrs = 1;
    cudaLaunchKernelEx(&cfg, kern, args...);
}

extern "C" void kernel_launch(void* const* d_in, const int* in_sizes, int n_in,
                              void* d_out, int out_size) {
    const float* x        = (const float*)d_in[0];
    const float* dc       = (const float*)d_in[1];
    const float* centers  = (const float*)d_in[2];
    const float* proj_w   = (const float*)d_in[3];
    const float* proj_b   = (const float*)d_in[4];
    const float* dc_param = (const float*)d_in[5];
    const float* cc       = (const float*)d_in[6];
    const float* gcn_w    = (const float*)d_in[7];
    const float* gcn_b    = (const float*)d_in[8];
    const float* out_w    = (const float*)d_in[9];
    const float* out_b    = (const float*)d_in[10];
    const float* w1       = (const float*)d_in[11];
    const float* b1       = (const float*)d_in[12];
    const float* w2       = (const float*)d_in[13];
    const float* b2       = (const float*)d_in[14];
    float* out = (float*)d_out;

    k1_prep<<<Bp / 2 + 1, 256>>>(x, dc, gcn_w, centers, proj_w, proj_b, cc);
    launch_pdl(k3_main, dim3(NJT, NIT), dim3(256), dc_param);
    launch_pdl(k4_emb, dim3(NCc), dim3(128),
               gcn_b, out_w, out_b, w1, b1, w2, b2, out);
    launch_pdl(k5_gather, dim3(256), dim3(128), out);
}

// round 8
// speedup vs baseline: 2.8264x; 1.0394x over previous
#include <cuda_runtime.h>
#include <cstdint>
#include <math.h>

// Problem constants
#define Bp   4096
#define Dd   19
#define Ff   64
#define NCc  256
#define HIDh 32
#define SQq  16
#define Nn   (Bp + NCc)
#define PD   20            // padded row stride (19 + 1 zero pad)
#define PD4  5             // PD/4 (float4 granules)

// Tiling
#define JT   128            // j per tile
#define NJT  (Nn / JT)      // 34
#define NPJT (Bp / JT)      // 32 patient-only tiles
#define IT   16             // centers per tile-task
#define NIT  (NCc / IT)     // 16
#define NTASK (NJT * NIT)   // 544

// Persistent grid
#define NBLK 148
#define NTHR 256

// Output offsets (floats)
#define OUT_GS  0
#define OUT_GE  (Bp * Dd)
#define OUT_GPE ((Bp + NCc) * Dd)
#define OUT_GL  (((2 * Bp) + NCc) * Dd)

typedef unsigned long long u64;

// -------- device scratch (no allocations allowed) --------
__device__ float4 g_x4[Nn * PD4];
__device__ float4 g_e4[Nn * PD4];
__device__ float  g_sq[Nn];
__device__ float4 g_g4[Nn * (HIDh / 4)];
__device__ float  g_partial[NJT * NCc * HIDh];
__device__ u64    g_key[Bp * NIT];         // [patient][center-tile]
__device__ float  g_ge[NCc * Dd];
__device__ float  g_sc[NCc * Dd];

// grid barrier state (zero-init at module load; returns to steady state)
__device__ unsigned g_bar_count;
__device__ volatile unsigned g_bar_sense;

__device__ __forceinline__ void grid_barrier(unsigned* sense0) {
    __syncthreads();
    if (threadIdx.x == 0) {
        unsigned next = *sense0 ^ 1u;
        __threadfence();                       // publish this block's writes
        if (atomicAdd(&g_bar_count, 1u) == gridDim.x - 1u) {
            g_bar_count = 0u;
            __threadfence();
            g_bar_sense = next;
        } else {
            while (g_bar_sense != next) { }
        }
        __threadfence();                       // acquire side
        *sense0 = next;
    }
    __syncthreads();
}

// packed f32x2 fma: d = a*b + d
__device__ __forceinline__ void ffma2(u64& d, u64 a, u64 b) {
    asm("fma.rn.f32x2 %0, %1, %2, %0;" : "+l"(d) : "l"(a), "l"(b));
}
__device__ __forceinline__ float lo32(u64 v) {
    return __uint_as_float((unsigned)(v & 0xFFFFFFFFull));
}
__device__ __forceinline__ float hi32(u64 v) {
    return __uint_as_float((unsigned)(v >> 32));
}
__device__ __forceinline__ u64 pack2(float a, float b) {
    u64 r;
    asm("mov.b64 %0, {%1, %2};" : "=l"(r) : "r"(__float_as_uint(a)), "r"(__float_as_uint(b)));
    return r;
}

// -------- shared memory (union across phases; max = P2 ~46.6KB) --------
struct SmP1 {
    float sxa[8][PD];       // per-warp x_avg
    float sw[Dd * HIDh];    // gcn_w
    float spw[61 * Dd];     // proj_w (blocks 0..7)
    float spb[Dd];
    float scx[32 * 61];     // staged center rows (blocks 0..7)
};
struct SmP2 {
    ulonglong2 sxu[JT * PD4];
    ulonglong2 seu[JT * PD4];
    u64   sg2[JT * 17];
    float ssq[JT];
    u64   skey[8][JT + 1];
};
struct SmP3 {
    float sp[2][4 * HIDh];
    float seh[2][HIDh];
    float semb[2][PD];
    float shq[2][SQq];
};
union SmemU {
    SmP1 p1;
    SmP2 p2;
    SmP3 p3;
};

// ============================================================
__global__ void __launch_bounds__(NTHR) fused_all(
        const float* __restrict__ x,
        const float* __restrict__ dc,
        const float* __restrict__ centers,
        const float* __restrict__ proj_w,
        const float* __restrict__ proj_b,
        const float* __restrict__ p_ptr,
        const float* __restrict__ cc,
        const float* __restrict__ gcn_w,
        const float* __restrict__ gcn_b,
        const float* __restrict__ out_w,
        const float* __restrict__ out_b,
        const float* __restrict__ w1,
        const float* __restrict__ b1,
        const float* __restrict__ w2,
        const float* __restrict__ b2,
        float* __restrict__ out) {
    __shared__ SmemU sm;
    __shared__ unsigned sense_sh;    // dummy home for sense (tid0 only)

    int tid = threadIdx.x;
    int wid = tid >> 5, lane = tid & 31;
    int bx = blockIdx.x;

    unsigned sense0;
    if (tid == 0) { sense0 = g_bar_sense; sense_sh = 0; }

    float p = *p_ptr;
    float c1 = 1.0f - p;

    float* gx = (float*)g_x4;
    float* ge = (float*)g_e4;
    float* gg = (float*)g_g4;

    // ======================= P1: prep =======================
    {
        if (bx < 8) {
            for (int i = tid; i < 61 * Dd; i += NTHR) sm.p1.spw[i] = proj_w[i];
            if (tid < Dd) sm.p1.spb[tid] = proj_b[tid];
            for (int i = tid; i < 32 * 61; i += NTHR)
                sm.p1.scx[i] = centers[bx * 32 * 61 + i];
        }
        for (int i = tid; i < Dd * HIDh; i += NTHR) sm.p1.sw[i] = gcn_w[i];
        __syncthreads();

        if (bx < 8) {
            // 32 centers: 8 threads per center
            int cl = tid >> 3, l8 = tid & 7;
            int c = bx * 32 + cl;
            float cp[Dd];
            #pragma unroll
            for (int k = 0; k < Dd; k++) cp[k] = 0.0f;
            for (int m = l8; m < 61; m += 8) {
                float cm = sm.p1.scx[cl * 61 + m];
                #pragma unroll
                for (int k = 0; k < Dd; k++) cp[k] += cm * sm.p1.spw[m * Dd + k];
            }
            // reduce over 8-lane group
            #pragma unroll
            for (int k = 0; k < Dd; k++) {
                cp[k] += __shfl_down_sync(0xffffffffu, cp[k], 4);
                cp[k] += __shfl_down_sync(0xffffffffu, cp[k], 2);
                cp[k] += __shfl_down_sync(0xffffffffu, cp[k], 1);
            }
            // add bias on leader, broadcast back to the group
            #pragma unroll
            for (int k = 0; k < Dd; k++) {
                float v = cp[k] + sm.p1.spb[k];
                cp[k] = __shfl_sync(0xffffffffu, v, lane & ~7);
            }
            int row = Bp + c;
            if (l8 == 0) {
                float s = 0.0f;
                #pragma unroll
                for (int k = 0; k < Dd; k++) s += cp[k] * cp[k];
                g_sq[row] = s;
                gx[row * PD + Dd] = 0.0f;
                ge[row * PD + Dd] = 0.0f;
            }
            for (int k = l8; k < Dd; k += 8) {
                gx[row * PD + k] = cp[k];
                ge[row * PD + k] = expf(1.0f - cc[c * Dd + k]);
            }
            // g: each lane does 4 h's
            #pragma unroll
            for (int j = 0; j < 4; j++) {
                int h = l8 * 4 + j;
                float acc = 0.0f;
                #pragma unroll
                for (int k = 0; k < Dd; k++) acc += cp[k] * sm.p1.sw[k * HIDh + h];
                gg[row * HIDh + h] = acc;
            }
        }

        // patients: warp-per-patient over all blocks
        int gw = bx * 8 + wid;                 // 0..1183
        for (int b = gw; b < Bp; b += NBLK * 8) {
            const float* xb = x + (size_t)b * (Dd * Ff);
            #pragma unroll
            for (int d = 0; d < Dd; d++) {
                float v = xb[d * Ff + lane] + xb[d * Ff + lane + 32];
                v += __shfl_down_sync(0xffffffffu, v, 16);
                v += __shfl_down_sync(0xffffffffu, v, 8);
                v += __shfl_down_sync(0xffffffffu, v, 4);
                v += __shfl_down_sync(0xffffffffu, v, 2);
                v += __shfl_down_sync(0xffffffffu, v, 1);
                if (lane == 0) sm.p1.sxa[wid][d] = v * (1.0f / 64.0f);
            }
            __syncwarp();
            float xa = (lane < Dd) ? sm.p1.sxa[wid][lane] : 0.0f;
            if (lane < PD) {
                gx[b * PD + lane] = xa;
                ge[b * PD + lane] = (lane < Dd) ? expf(1.0f - dc[b * Dd + lane]) : 0.0f;
            }
            float s = xa * xa;
            s += __shfl_down_sync(0xffffffffu, s, 16);
            s += __shfl_down_sync(0xffffffffu, s, 8);
            s += __shfl_down_sync(0xffffffffu, s, 4);
            s += __shfl_down_sync(0xffffffffu, s, 2);
            s += __shfl_down_sync(0xffffffffu, s, 1);
            if (lane == 0) g_sq[b] = s;
            // g = x_avg @ gcn_w : lane = h
            float acc = 0.0f;
            #pragma unroll
            for (int k = 0; k < Dd; k++) acc += sm.p1.sxa[wid][k] * sm.p1.sw[k * HIDh + lane];
            gg[b * HIDh + lane] = acc;
            __syncwarp();
        }
    }

    grid_barrier(&sense0);

    // ======================= P2: adjacency + adj@g + keys =======================
    {
        const ulonglong2* gxu = (const ulonglong2*)g_x4;
        const ulonglong2* geu = (const ulonglong2*)g_e4;
        int cp = tid >> 5, s = tid & 31;

        for (int t = bx; t < NTASK; t += NBLK) {
            int jt = t / NIT, it = t - (t / NIT) * NIT;
            int j0 = jt * JT;
            bool patient_tile = (jt < NPJT);

            __syncthreads();   // close previous task's smem reads

            for (int i = tid; i < JT * PD4; i += NTHR) {
                sm.p2.sxu[i] = gxu[j0 * PD4 + i];
                sm.p2.seu[i] = geu[j0 * PD4 + i];
            }
            for (int i = tid; i < JT * (HIDh / 4); i += NTHR) {
                int j = i >> 3, q = i & 7;
                float4 gv = g_g4[(size_t)(j0 + j) * (HIDh / 4) + q];
                sm.p2.sg2[j * 17 + q * 2 + 0] = pack2(gv.x, gv.y);
                sm.p2.sg2[j * 17 + q * 2 + 1] = pack2(gv.z, gv.w);
            }
            if (tid < JT) sm.p2.ssq[tid] = g_sq[j0 + tid];

            int cA = it * IT + cp * 2;
            int cB = cA + 1;
            int cgA = Bp + cA, cgB = Bp + cB;

            ulonglong2 xA[PD4], eA[PD4], xB[PD4], eB[PD4];
            #pragma unroll
            for (int q = 0; q < PD4; q++) {
                xA[q] = gxu[cgA * PD4 + q];
                eA[q] = geu[cgA * PD4 + q];
                xB[q] = gxu[cgB * PD4 + q];
                eB[q] = geu[cgB * PD4 + q];
            }
            float sqA = g_sq[cgA], sqB = g_sq[cgB];
            __syncthreads();

            u64 accA[HIDh / 2], accB[HIDh / 2];
            #pragma unroll
            for (int h = 0; h < HIDh / 2; h++) { accA[h] = 0ull; accB[h] = 0ull; }

            #pragma unroll
            for (int tt = 0; tt < JT / 32; tt++) {
                int j = s + 32 * tt;
                u64 dxA2 = 0ull, deA2 = 0ull, dxB2 = 0ull, deB2 = 0ull;
                #pragma unroll
                for (int q = 0; q < PD4; q++) {
                    ulonglong2 v = sm.p2.sxu[j * PD4 + q];
                    ulonglong2 w = sm.p2.seu[j * PD4 + q];
                    ffma2(dxA2, xA[q].x, v.x);  ffma2(dxA2, xA[q].y, v.y);
                    ffma2(deA2, eA[q].x, w.x);  ffma2(deA2, eA[q].y, w.y);
                    ffma2(dxB2, xB[q].x, v.x);  ffma2(dxB2, xB[q].y, v.y);
                    ffma2(deB2, eB[q].x, w.x);  ffma2(deB2, eB[q].y, w.y);
                }
                float dxA = lo32(dxA2) + hi32(dxA2);
                float deA = lo32(deA2) + hi32(deA2);
                float dxB = lo32(dxB2) + hi32(dxB2);
                float deB = lo32(deB2) + hi32(deB2);

                int jg = j0 + j;
                float denA = c1 * (sqA + sm.p2.ssq[j] - 2.0f * dxA) + p * deA;
                float denB = c1 * (sqB + sm.p2.ssq[j] - 2.0f * dxB) + p * deB;
                float aA = (jg == cgA) ? 1.0f : __fdividef((float)Dd, denA);
                float aB = (jg == cgB) ? 1.0f : __fdividef((float)Dd, denB);

                if (patient_tile) {
                    u64 kA = (((u64)__float_as_uint(denA)) << 32) | (unsigned)cA;
                    u64 kB = (((u64)__float_as_uint(denB)) << 32) | (unsigned)cB;
                    sm.p2.skey[cp][j] = (kA < kB) ? kA : kB;
                }

                u64 a2A = pack2(aA, aA);
                u64 a2B = pack2(aB, aB);
                #pragma unroll
                for (int h = 0; h < HIDh / 2; h++) {
                    u64 gv = sm.p2.sg2[j * 17 + h];
                    ffma2(accA[h], a2A, gv);
                    ffma2(accB[h], a2B, gv);
                }
            }

            if (patient_tile) {
                __syncthreads();
                if (tid < JT) {
                    u64 m = sm.p2.skey[0][tid];
                    #pragma unroll
                    for (int q = 1; q < 8; q++) {
                        u64 v = sm.p2.skey[q][tid];
                        if (v < m) m = v;
                    }
                    g_key[(size_t)(j0 + tid) * NIT + it] = m;
                }
            }

            float fA[HIDh], fB[HIDh];
            #pragma unroll
            for (int h = 0; h < HIDh / 2; h++) {
                fA[2 * h] = lo32(accA[h]);  fA[2 * h + 1] = hi32(accA[h]);
                fB[2 * h] = lo32(accB[h]);  fB[2 * h + 1] = hi32(accB[h]);
            }
            #pragma unroll
            for (int d = 16; d >= 1; d >>= 1) {
                #pragma unroll
                for (int i = 0; i < d; i++) {
                    float sendA = (s & d) ? fA[i] : fA[i + d];
                    float sendB = (s & d) ? fB[i] : fB[i + d];
                    float recvA = __shfl_xor_sync(0xffffffffu, sendA, d);
                    float recvB = __shfl_xor_sync(0xffffffffu, sendB, d);
                    fA[i] = ((s & d) ? fA[i + d] : fA[i]) + recvA;
                    fB[i] = ((s & d) ? fB[i + d] : fB[i]) + recvB;
                }
            }
            g_partial[((size_t)jt * NCc + cA) * HIDh + s] = fA[0];
            g_partial[((size_t)jt * NCc + cB) * HIDh + s] = fB[0];
        }
    }

    grid_barrier(&sense0);

    // ======================= P3: center MLP chain =======================
    {
        int half = wid >> 2;                 // 0/1
        int w4 = wid & 3;
        int h = lane;
        int c = bx * 2 + half;
        bool active = (c < NCc);

        float ps = 0.0f;
        if (active) {
            int jt0 = w4 * 9;
            int jt1 = (w4 == 3) ? NJT : jt0 + 9;
            const float* pp = &g_partial[(size_t)c * HIDh + h];
            #pragma unroll 9
            for (int jt = jt0; jt < jt1; jt++)
                ps += pp[(size_t)jt * (NCc * HIDh)];
        }
        sm.p3.sp[half][w4 * HIDh + h] = ps;
        __syncthreads();

        if (w4 == 0 && active) {
            const float* spv = sm.p3.sp[half];
            float eh = gcn_b[h] + spv[h] + spv[HIDh + h] + spv[2 * HIDh + h] + spv[3 * HIDh + h];
            sm.p3.seh[half][h] = eh;
            __syncwarp();

            if (h < Dd) {
                float v = out_b[h];
                #pragma unroll
                for (int q = 0; q < HIDh; q++) v += sm.p3.seh[half][q] * out_w[q * Dd + h];
                v = 1.0f / (1.0f + expf(-v));
                sm.p3.semb[half][h] = v;
                g_ge[c * Dd + h] = v;
                out[OUT_GE + c * Dd + h] = v;
            }
            __syncwarp();

            if (h < SQq) {
                float v = b1[h];
                #pragma unroll
                for (int k = 0; k < Dd; k++) v += sm.p3.semb[half][k] * w1[k * SQq + h];
                sm.p3.shq[half][h] = 0.5f * v * (1.0f + erff(v * 0.70710678118654752f));
            }
            __syncwarp();

            if (h < Dd) {
                float v = b2[h];
                #pragma unroll
                for (int q = 0; q < SQq; q++) v += sm.p3.shq[half][q] * w2[q * Dd + h];
                g_sc[c * Dd + h] = 1.0f / (1.0f + expf(-v));
            }
        }
    }

    grid_barrier(&sense0);

    // ======================= P4: label + gather =======================
    if (bx < Bp / 32) {
        int pl = tid >> 3, l8 = tid & 7;
        int jp = bx * 32 + pl;

        ulonglong2 kv = ((const ulonglong2*)g_key)[(size_t)jp * 8 + l8];
        u64 best = (kv.x < kv.y) ? kv.x : kv.y;
        u64 o;
        o = __shfl_xor_sync(0xffffffffu, best, 1); if (o < best) best = o;
        o = __shfl_xor_sync(0xffffffffu, best, 2); if (o < best) best = o;
        o = __shfl_xor_sync(0xffffffffu, best, 4); if (o < best) best = o;
        best = __shfl_sync(0xffffffffu, best, lane & ~7);

        int label = (int)(unsigned)(best & 0xFFFFFFFFull);
        #pragma unroll
        for (int k = l8; k < Dd; k += 8) {
            out[OUT_GS + jp * Dd + k]  = g_sc[label * Dd + k];
            out[OUT_GPE + jp * Dd + k] = g_ge[label * Dd + k];
        }
        if (l8 == 0) out[OUT_GL + jp] = (float)label;
    }
}

// ============================================================
extern "C" void kernel_launch(void* const* d_in, const int* in_sizes, int n_in,
                              void* d_out, int out_size) {
    const float* x        = (const float*)d_in[0];
    const float* dc       = (const float*)d_in[1];
    const float* centers  = (const float*)d_in[2];
    const float* proj_w   = (const float*)d_in[3];
    const float* proj_b   = (const float*)d_in[4];
    const float* dc_param = (const float*)d_in[5];
    const float* cc       = (const float*)d_in[6];
    const float* gcn_w    = (const float*)d_in[7];
    const float* gcn_b    = (const float*)d_in[8];
    const float* out_w    = (const float*)d_in[9];
    const float* out_b    = (const float*)d_in[10];
    const float* w1       = (const float*)d_in[11];
    const float* b1       = (const float*)d_in[12];
    const float* w2       = (const float*)d_in[13];
    const float* b2       = (const float*)d_in[14];
    float* out = (float*)d_out;

    fused_all<<<NBLK, NTHR>>>(x, dc, centers, proj_w, proj_b, dc_param, cc,
                              gcn_w, gcn_b, out_w, out_b, w1, b1, w2, b2, out);
}